// round 2
// baseline (speedup 1.0000x reference)
#include <cuda_runtime.h>
#include <math.h>
#include <stdint.h>

#define BATCH   4
#define SEQ     2048
#define DMODEL  1024
#define NHEAD   16
#define HDIM    64
#define ROWS    (BATCH * SEQ)        /* 8192  */
#define QKVCOLS (3 * DMODEL)         /* 3072  */
#define SCALE_C 0.125f               /* 64^-0.5 */

/* Scratch (no cudaMalloc allowed): QKV matrix [8192,3072] and attention
   output in [B,S,D] layout [8192,1024]. */
__device__ float g_qkv[(size_t)ROWS * QKVCOLS];
__device__ float g_attn[(size_t)ROWS * DMODEL];

/* ------------------------------------------------------------------ */
/* SGEMM + bias:  C[M,N] = A[M,K] * B[K,N] + bias[N]                  */
/* 128x128 block tile, BK=8, 256 threads, 8x8 micro-tile.             */
/* M,N multiples of 128; K multiple of 8 (true for all our shapes).   */
/* ------------------------------------------------------------------ */
__global__ __launch_bounds__(256) void sgemm_bias_kernel(
    const float* __restrict__ A, const float* __restrict__ B,
    const float* __restrict__ bias, float* __restrict__ C,
    int M, int N, int K)
{
    __shared__ float As[8][128];   /* transposed A tile: As[k][m] */
    __shared__ float Bs[8][128];   /* natural B tile:    Bs[k][n] */

    const int tid = threadIdx.x;
    const int tx  = tid & 15;       /* column group */
    const int ty  = tid >> 4;       /* row group    */
    const int m0  = blockIdx.y << 7;
    const int n0  = blockIdx.x << 7;

    const int arow = tid >> 1;            /* 0..127 */
    const int akq  = (tid & 1) << 2;      /* 0 or 4 */
    const int brow = tid >> 5;            /* 0..7   */
    const int bcol = (tid & 31) << 2;     /* 0..124 */

    const float* Ap = A + (size_t)(m0 + arow) * K + akq;
    const float* Bp = B + (size_t)brow * N + n0 + bcol;

    float acc[8][8];
#pragma unroll
    for (int i = 0; i < 8; i++)
#pragma unroll
        for (int j = 0; j < 8; j++) acc[i][j] = 0.f;

    for (int k0 = 0; k0 < K; k0 += 8) {
        float4 av = *(const float4*)(Ap + k0);
        float4 bv = *(const float4*)(Bp + (size_t)k0 * N);
        __syncthreads();
        As[akq + 0][arow] = av.x;
        As[akq + 1][arow] = av.y;
        As[akq + 2][arow] = av.z;
        As[akq + 3][arow] = av.w;
        *(float4*)&Bs[brow][bcol] = bv;
        __syncthreads();
#pragma unroll
        for (int k = 0; k < 8; k++) {
            float4 a0 = *(const float4*)&As[k][(ty << 3)];
            float4 a1 = *(const float4*)&As[k][(ty << 3) + 4];
            float4 b0 = *(const float4*)&Bs[k][(tx << 3)];
            float4 b1 = *(const float4*)&Bs[k][(tx << 3) + 4];
            float a[8] = {a0.x, a0.y, a0.z, a0.w, a1.x, a1.y, a1.z, a1.w};
            float b[8] = {b0.x, b0.y, b0.z, b0.w, b1.x, b1.y, b1.z, b1.w};
#pragma unroll
            for (int i = 0; i < 8; i++)
#pragma unroll
                for (int j = 0; j < 8; j++)
                    acc[i][j] = fmaf(a[i], b[j], acc[i][j]);
        }
    }

    float4 bs0 = *(const float4*)(bias + n0 + (tx << 3));
    float4 bs1 = *(const float4*)(bias + n0 + (tx << 3) + 4);
    const float bb[8] = {bs0.x, bs0.y, bs0.z, bs0.w, bs1.x, bs1.y, bs1.z, bs1.w};

#pragma unroll
    for (int i = 0; i < 8; i++) {
        size_t row = (size_t)(m0 + (ty << 3) + i);
        float4 o0 = make_float4(acc[i][0] + bb[0], acc[i][1] + bb[1],
                                acc[i][2] + bb[2], acc[i][3] + bb[3]);
        float4 o1 = make_float4(acc[i][4] + bb[4], acc[i][5] + bb[5],
                                acc[i][6] + bb[6], acc[i][7] + bb[7]);
        *(float4*)(C + row * N + n0 + (tx << 3))     = o0;
        *(float4*)(C + row * N + n0 + (tx << 3) + 4) = o1;
    }
}

/* ------------------------------------------------------------------ */
/* Flash attention: one block = 128 query rows of one (b,h).          */
/* Q/K/V read straight out of the fused QKV matrix (stride 3072).     */
/* Smem tiles XOR-swizzled on 16B granules -> conflict-free LDS.128.  */
/* ------------------------------------------------------------------ */
#define FLASH_SMEM ((3 * 128 * 64 + 128 * 128) * 4)   /* 160 KB */

__device__ __forceinline__ int swz(int row, int g) {
    /* physical float offset of 16B granule g within swizzled row */
    return ((g ^ ((row >> 2) & 7)) << 2);
}

__global__ __launch_bounds__(256) void flash_attn_kernel(
    const float* __restrict__ qkv, float* __restrict__ out)
{
    extern __shared__ float sm[];
    float* Qs = sm;                    /* [128][64]  swizzled */
    float* Ks = Qs + 128 * 64;         /* [128][64]  swizzled */
    float* Vs = Ks + 128 * 64;         /* [128][64]  swizzled */
    float* Ps = Vs + 128 * 64;         /* [128][128] swizzled */

    const int tid = threadIdx.x;
    const int tx  = tid & 15;
    const int ty  = tid >> 4;
    const int q0  = blockIdx.x << 7;
    const int b   = blockIdx.y >> 4;
    const int h   = blockIdx.y & 15;
    const size_t base = (size_t)b * SEQ;
    const int qoff = h * HDIM;

    int rowIdx[8];
#pragma unroll
    for (int i = 0; i < 4; i++) {
        rowIdx[i]     = (ty << 2) + i;
        rowIdx[i + 4] = 64 + (ty << 2) + i;
    }

    /* load Q tile: 128 rows x 64 cols, 2048 float4 */
    for (int l = tid; l < 128 * 16; l += 256) {
        int r = l >> 4, g = l & 15;
        float4 v = *(const float4*)(qkv + (base + q0 + r) * QKVCOLS + qoff + (g << 2));
        *(float4*)(Qs + r * 64 + swz(r, g)) = v;
    }

    float m_i[8], l_i[8], acc[8][4];
#pragma unroll
    for (int i = 0; i < 8; i++) {
        m_i[i] = -1e30f;
        l_i[i] = 0.f;
#pragma unroll
        for (int j = 0; j < 4; j++) acc[i][j] = 0.f;
    }

    for (int kt = 0; kt < SEQ; kt += 128) {
        __syncthreads();   /* prev PV done (and Q stores on first iter) */
        for (int l = tid; l < 128 * 16; l += 256) {
            int r = l >> 4, g = l & 15;
            size_t grow = (base + kt + r) * QKVCOLS;
            int so = r * 64 + swz(r, g);
            float4 kv = *(const float4*)(qkv + grow + DMODEL + qoff + (g << 2));
            *(float4*)(Ks + so) = kv;
            float4 vv = *(const float4*)(qkv + grow + 2 * DMODEL + qoff + (g << 2));
            *(float4*)(Vs + so) = vv;
        }
        __syncthreads();

        /* ---- S = Q * K^T ---- */
        float s[8][8];
#pragma unroll
        for (int i = 0; i < 8; i++)
#pragma unroll
            for (int j = 0; j < 8; j++) s[i][j] = 0.f;

#pragma unroll 1
        for (int kk = 0; kk < 64; kk += 4) {
            const int g = kk >> 2;
            float4 a[8], bb[8];
#pragma unroll
            for (int i = 0; i < 8; i++) {
                int r = rowIdx[i];
                a[i] = *(const float4*)(Qs + r * 64 + swz(r, g));
            }
#pragma unroll
            for (int j = 0; j < 4; j++) {
                int r1 = (tx << 2) + j;
                bb[j] = *(const float4*)(Ks + r1 * 64 + swz(r1, g));
                int r2 = 64 + (tx << 2) + j;
                bb[j + 4] = *(const float4*)(Ks + r2 * 64 + swz(r2, g));
            }
#pragma unroll
            for (int i = 0; i < 8; i++)
#pragma unroll
                for (int j = 0; j < 8; j++) {
                    s[i][j] = fmaf(a[i].x, bb[j].x, s[i][j]);
                    s[i][j] = fmaf(a[i].y, bb[j].y, s[i][j]);
                    s[i][j] = fmaf(a[i].z, bb[j].z, s[i][j]);
                    s[i][j] = fmaf(a[i].w, bb[j].w, s[i][j]);
                }
        }

        /* ---- online softmax, write P ---- */
#pragma unroll
        for (int i = 0; i < 8; i++) {
            float mx = s[i][0];
#pragma unroll
            for (int j = 1; j < 8; j++) mx = fmaxf(mx, s[i][j]);
            mx *= SCALE_C;
#pragma unroll
            for (int o = 8; o; o >>= 1)
                mx = fmaxf(mx, __shfl_xor_sync(0xffffffffu, mx, o, 16));
            float mnew  = fmaxf(m_i[i], mx);
            float alpha = __expf(m_i[i] - mnew);
            m_i[i] = mnew;

            float p[8];
            float rsum = 0.f;
#pragma unroll
            for (int j = 0; j < 8; j++) {
                p[j] = __expf(fmaf(s[i][j], SCALE_C, -mnew));
                rsum += p[j];
            }
#pragma unroll
            for (int o = 8; o; o >>= 1)
                rsum += __shfl_xor_sync(0xffffffffu, rsum, o, 16);
            l_i[i] = l_i[i] * alpha + rsum;
#pragma unroll
            for (int j = 0; j < 4; j++) acc[i][j] *= alpha;

            int r = rowIdx[i];
            *(float4*)(Ps + r * 128 + swz(r, tx))      = make_float4(p[0], p[1], p[2], p[3]);
            *(float4*)(Ps + r * 128 + swz(r, 16 + tx)) = make_float4(p[4], p[5], p[6], p[7]);
        }
        __syncthreads();

        /* ---- O += P * V ---- */
#pragma unroll 1
        for (int kk = 0; kk < 128; kk += 4) {
            const int gsw = (kk >> 2) & 7;
            const float* vb = Vs + kk * 64 + ((tx ^ gsw) << 2);
            float4 b0 = *(const float4*)(vb);
            float4 b1 = *(const float4*)(vb + 64);
            float4 b2 = *(const float4*)(vb + 128);
            float4 b3 = *(const float4*)(vb + 192);
#pragma unroll
            for (int i = 0; i < 8; i++) {
                int r = rowIdx[i];
                float4 pv = *(const float4*)(Ps + r * 128 + swz(r, kk >> 2));
                acc[i][0] = fmaf(pv.x, b0.x, fmaf(pv.y, b1.x, fmaf(pv.z, b2.x, fmaf(pv.w, b3.x, acc[i][0]))));
                acc[i][1] = fmaf(pv.x, b0.y, fmaf(pv.y, b1.y, fmaf(pv.z, b2.y, fmaf(pv.w, b3.y, acc[i][1]))));
                acc[i][2] = fmaf(pv.x, b0.z, fmaf(pv.y, b1.z, fmaf(pv.z, b2.z, fmaf(pv.w, b3.z, acc[i][2]))));
                acc[i][3] = fmaf(pv.x, b0.w, fmaf(pv.y, b1.w, fmaf(pv.z, b2.w, fmaf(pv.w, b3.w, acc[i][3]))));
            }
        }
    }

    /* epilogue: normalize and write to [B,S,D] layout */
#pragma unroll
    for (int i = 0; i < 8; i++) {
        int r = rowIdx[i];
        float inv = 1.f / l_i[i];
        float4 o = make_float4(acc[i][0] * inv, acc[i][1] * inv,
                               acc[i][2] * inv, acc[i][3] * inv);
        *(float4*)(out + (base + q0 + r) * DMODEL + qoff + (tx << 2)) = o;
    }
}

/* ------------------------------------------------------------------ */
extern "C" void kernel_launch(void* const* d_in, const int* in_sizes, int n_in,
                              void* d_out, int out_size)
{
    (void)in_sizes; (void)n_in; (void)out_size;
    const float* x     = (const float*)d_in[0];
    const float* w_qkv = (const float*)d_in[1];
    const float* b_qkv = (const float*)d_in[2];
    const float* w_out = (const float*)d_in[3];
    const float* b_out = (const float*)d_in[4];
    float* out = (float*)d_out;

    float *qkv_p = nullptr, *attn_p = nullptr;
    cudaGetSymbolAddress((void**)&qkv_p, g_qkv);
    cudaGetSymbolAddress((void**)&attn_p, g_attn);

    cudaFuncSetAttribute(flash_attn_kernel,
                         cudaFuncAttributeMaxDynamicSharedMemorySize, FLASH_SMEM);

    /* 1) QKV projection: [8192,1024] x [1024,3072] + bias */
    sgemm_bias_kernel<<<dim3(QKVCOLS / 128, ROWS / 128), 256>>>(
        x, w_qkv, b_qkv, qkv_p, ROWS, QKVCOLS, DMODEL);

    /* 2) flash attention over heads */
    flash_attn_kernel<<<dim3(SEQ / 128, BATCH * NHEAD), 256, FLASH_SMEM>>>(
        qkv_p, attn_p);

    /* 3) output projection: [8192,1024] x [1024,1024] + bias */
    sgemm_bias_kernel<<<dim3(DMODEL / 128, ROWS / 128), 256>>>(
        attn_p, w_out, b_out, out, ROWS, DMODEL, DMODEL);
}

// round 6
// speedup vs baseline: 2.1773x; 2.1773x over previous
#include <cuda_runtime.h>
#include <cuda_bf16.h>
#include <stdint.h>

typedef __nv_bfloat16  bf16;
typedef __nv_bfloat162 bf162;

#define BATCH 4
#define SEQ   2048
#define DM    1024
#define NH    16
#define HD    64
#define ROWS  8192
#define QC    3072
/* 0.125 * log2(e) : softmax computed in base-2 domain */
#define KSCL  0.1803368801111204f

/* ---------------- scratch (__device__ globals) --------------------- */
__device__ bf16 g_xh[(size_t)ROWS * DM];
__device__ bf16 g_xl[(size_t)ROWS * DM];
__device__ bf16 g_wqh[(size_t)QC * DM];
__device__ bf16 g_wql[(size_t)QC * DM];
__device__ bf16 g_woh[(size_t)DM * DM];
__device__ bf16 g_wol[(size_t)DM * DM];
__device__ bf16 g_qkvh[(size_t)ROWS * QC];
__device__ bf16 g_qkvl[(size_t)ROWS * QC];
__device__ bf16 g_ah[(size_t)ROWS * DM];
__device__ bf16 g_al[(size_t)ROWS * DM];

/* ---------------- helpers ------------------------------------------ */
__device__ __forceinline__ uint32_t s2u(const void* p) {
    uint32_t a;
    asm("{ .reg .u64 t; cvta.to.shared.u64 t, %1; cvt.u32.u64 %0, t; }"
        : "=r"(a) : "l"(p));
    return a;
}
__device__ __forceinline__ void ldsm4(uint32_t* d, uint32_t a) {
    asm volatile("ldmatrix.sync.aligned.m8n8.x4.shared.b16 {%0,%1,%2,%3}, [%4];"
        : "=r"(d[0]), "=r"(d[1]), "=r"(d[2]), "=r"(d[3]) : "r"(a));
}
__device__ __forceinline__ void ldsm4t(uint32_t* d, uint32_t a) {
    asm volatile("ldmatrix.sync.aligned.m8n8.x4.trans.shared.b16 {%0,%1,%2,%3}, [%4];"
        : "=r"(d[0]), "=r"(d[1]), "=r"(d[2]), "=r"(d[3]) : "r"(a));
}
__device__ __forceinline__ void mmabf(float* c, const uint32_t* a,
                                      uint32_t b0, uint32_t b1) {
    asm volatile("mma.sync.aligned.m16n8k16.row.col.f32.bf16.bf16.f32 "
        "{%0,%1,%2,%3}, {%4,%5,%6,%7}, {%8,%9}, {%0,%1,%2,%3};"
        : "+f"(c[0]), "+f"(c[1]), "+f"(c[2]), "+f"(c[3])
        : "r"(a[0]), "r"(a[1]), "r"(a[2]), "r"(a[3]), "r"(b0), "r"(b1));
}
/* exp2 on the FMA pipe (deg-5 poly around 0, |f|<=0.5, rel err ~2e-6) */
__device__ __forceinline__ float exp2p(float x) {
    x = fmaxf(x, -100.f);
    int i = __float2int_rn(x);
    float f = x - (float)i;
    float p = fmaf(1.3333558146e-3f, f, 9.6181291076e-3f);
    p = fmaf(p, f, 5.5504108664e-2f);
    p = fmaf(p, f, 2.4022650696e-1f);
    p = fmaf(p, f, 6.9314718056e-1f);
    p = fmaf(p, f, 1.0f);
    return p * __int_as_float((i + 127) << 23);
}
/* split (v0,v1) fp32 -> bf16x2 hi (round-nearest) + bf16x2 residual */
__device__ __forceinline__ void split2(float v0, float v1,
                                       uint32_t& hi, uint32_t& lo) {
    bf16 h0 = __float2bfloat16(v0), h1 = __float2bfloat16(v1);
    bf162 H; H.x = h0; H.y = h1;
    bf162 L;
    L.x = __float2bfloat16(v0 - __bfloat162float(h0));
    L.y = __float2bfloat16(v1 - __bfloat162float(h1));
    hi = *(uint32_t*)&H; lo = *(uint32_t*)&L;
}

/* ---------------- fp32 -> bf16 hi/lo split kernels ------------------ */
__global__ __launch_bounds__(256) void split_kernel(
    const float* __restrict__ in, bf16* __restrict__ hi,
    bf16* __restrict__ lo, int n4)
{
    int i = blockIdx.x * 256 + threadIdx.x;
    if (i >= n4) return;
    float4 v = ((const float4*)in)[i];
    uint32_t h0, l0, h1, l1;
    split2(v.x, v.y, h0, l0);
    split2(v.z, v.w, h1, l1);
    ((uint32_t*)hi)[2 * i] = h0; ((uint32_t*)hi)[2 * i + 1] = h1;
    ((uint32_t*)lo)[2 * i] = l0; ((uint32_t*)lo)[2 * i + 1] = l1;
}

/* w [1024, Ncols] fp32 -> wT hi/lo [Ncols, 1024] bf16 (K contiguous) */
__global__ __launch_bounds__(256) void transpose_split_kernel(
    const float* __restrict__ w, bf16* __restrict__ th,
    bf16* __restrict__ tl, int Ncols)
{
    __shared__ float t[32][33];
    int n0 = blockIdx.x * 32, k0 = blockIdx.y * 32;
    int tx = threadIdx.x, ty = threadIdx.y;   /* block (32,8) */
#pragma unroll
    for (int i = 0; i < 4; i++)
        t[ty + 8 * i][tx] = w[(size_t)(k0 + ty + 8 * i) * Ncols + n0 + tx];
    __syncthreads();
#pragma unroll
    for (int i = 0; i < 4; i++) {
        float v = t[tx][ty + 8 * i];
        bf16 h = __float2bfloat16(v);
        size_t o = (size_t)(n0 + ty + 8 * i) * DM + k0 + tx;
        th[o] = h;
        tl[o] = __float2bfloat16(v - __bfloat162float(h));
    }
}

/* ------------------------------------------------------------------ */
/* GEMM via mma.sync: C[M,N] = A[M,K] * B[N,K]^T + bias, 3-term split. */
/* Tile 128x128, BK=32, 8 warps (2x4), warp tile 64x32.                */
/* ------------------------------------------------------------------ */
#define GEMM_SMEM (4 * 128 * 32 * 2)   /* 32 KB */

template<int SPLIT_OUT>
__global__ __launch_bounds__(256, 1) void gemm_mma_kernel(
    const bf16* __restrict__ Ah, const bf16* __restrict__ Al,
    const bf16* __restrict__ Bh, const bf16* __restrict__ Bl,
    const float* __restrict__ bias, float* __restrict__ Cf,
    bf16* __restrict__ Ch, bf16* __restrict__ Cl, int N)
{
    extern __shared__ __align__(1024) char sm[];
    const uint32_t sb = s2u(sm);
    const int tid = threadIdx.x, w = tid >> 5, lane = tid & 31;
    const int wm = w >> 2, wn = w & 3;
    const int m0 = blockIdx.y << 7, n0 = blockIdx.x << 7;

    const int lr  = lane & 15;                       /* A-type ld row  */
    const int lg  = lane >> 4;                       /* A-type granule */
    const int brr = (lane & 7) + ((lane & 16) >> 1); /* B-type ld row  */
    const int bg  = (lane >> 3) & 1;                 /* B-type granule */
    const int g4  = lane >> 2, l4 = lane & 3;

    float c[4][4][4];
#pragma unroll
    for (int i = 0; i < 4; i++)
#pragma unroll
        for (int j = 0; j < 4; j++)
#pragma unroll
            for (int e = 0; e < 4; e++) c[i][j][e] = 0.f;

    const int r  = tid >> 1;              /* smem row this thread fills */
    const int gb = (tid & 1) << 1;        /* granule pair base          */
    uint4 st[8];

    auto LD = [&](int k0) {
        size_t ar = (size_t)(m0 + r) * DM + k0 + gb * 8;
        size_t br = (size_t)(n0 + r) * DM + k0 + gb * 8;
        st[0] = *(const uint4*)(Ah + ar); st[1] = *(const uint4*)(Ah + ar + 8);
        st[2] = *(const uint4*)(Al + ar); st[3] = *(const uint4*)(Al + ar + 8);
        st[4] = *(const uint4*)(Bh + br); st[5] = *(const uint4*)(Bh + br + 8);
        st[6] = *(const uint4*)(Bl + br); st[7] = *(const uint4*)(Bl + br + 8);
    };
    auto STs = [&]() {
        int o0 = r * 64 + ((gb ^ (r & 3)) << 4);
        int o1 = r * 64 + (((gb + 1) ^ (r & 3)) << 4);
        *(uint4*)(sm + o0)         = st[0]; *(uint4*)(sm + o1)         = st[1];
        *(uint4*)(sm + 8192 + o0)  = st[2]; *(uint4*)(sm + 8192 + o1)  = st[3];
        *(uint4*)(sm + 16384 + o0) = st[4]; *(uint4*)(sm + 16384 + o1) = st[5];
        *(uint4*)(sm + 24576 + o0) = st[6]; *(uint4*)(sm + 24576 + o1) = st[7];
    };

    LD(0);
#pragma unroll 1
    for (int s = 0; s < 32; s++) {
        __syncthreads();
        STs();
        __syncthreads();
        if (s < 31) LD((s + 1) * 32);
#pragma unroll
        for (int ks = 0; ks < 2; ks++) {
            uint32_t ah[4][4], al[4][4];
#pragma unroll
            for (int im = 0; im < 4; im++) {
                int ar = wm * 64 + im * 16 + lr;
                int offA = ar * 64 + (((2 * ks + lg) ^ (ar & 3)) << 4);
                ldsm4(ah[im], sb + offA);
                ldsm4(al[im], sb + 8192 + offA);
            }
#pragma unroll
            for (int jp = 0; jp < 2; jp++) {
                int rb = wn * 32 + jp * 16 + brr;
                int offB = rb * 64 + (((2 * ks + bg) ^ (rb & 3)) << 4);
                uint32_t bh4[4], bl4[4];
                ldsm4(bh4, sb + 16384 + offB);
                ldsm4(bl4, sb + 24576 + offB);
#pragma unroll
                for (int im = 0; im < 4; im++) {
                    mmabf(c[im][2 * jp],     ah[im], bh4[0], bh4[1]);
                    mmabf(c[im][2 * jp],     ah[im], bl4[0], bl4[1]);
                    mmabf(c[im][2 * jp],     al[im], bh4[0], bh4[1]);
                    mmabf(c[im][2 * jp + 1], ah[im], bh4[2], bh4[3]);
                    mmabf(c[im][2 * jp + 1], ah[im], bl4[2], bl4[3]);
                    mmabf(c[im][2 * jp + 1], al[im], bh4[2], bh4[3]);
                }
            }
        }
    }

    /* epilogue */
#pragma unroll
    for (int im = 0; im < 4; im++) {
#pragma unroll
        for (int jn = 0; jn < 4; jn++) {
            int row = m0 + wm * 64 + im * 16 + g4;
            int col = n0 + wn * 32 + jn * 8 + l4 * 2;
            float2 bb = *(const float2*)(bias + col);
            float v0 = c[im][jn][0] + bb.x, v1 = c[im][jn][1] + bb.y;
            float v2 = c[im][jn][2] + bb.x, v3 = c[im][jn][3] + bb.y;
            if (SPLIT_OUT) {
                uint32_t h, l;
                split2(v0, v1, h, l);
                *(uint32_t*)(Ch + (size_t)row * N + col) = h;
                *(uint32_t*)(Cl + (size_t)row * N + col) = l;
                split2(v2, v3, h, l);
                *(uint32_t*)(Ch + (size_t)(row + 8) * N + col) = h;
                *(uint32_t*)(Cl + (size_t)(row + 8) * N + col) = l;
            } else {
                *(float2*)(Cf + (size_t)row * N + col)       = make_float2(v0, v1);
                *(float2*)(Cf + (size_t)(row + 8) * N + col) = make_float2(v2, v3);
            }
        }
    }
}

/* ------------------------------------------------------------------ */
/* Flash attention, FA2-style on mma.sync. BM=BN=128, 8 warps x 16 rows*/
/* S: 3-term split; P: 2-term split; PV: PhVh + PlVh + PhVl.           */
/* ------------------------------------------------------------------ */
#define FLASH_SMEM (6 * 128 * 64 * 2)   /* 96 KB */

__global__ __launch_bounds__(256, 1) void flash_mma_kernel(
    const bf16* __restrict__ qh, const bf16* __restrict__ ql,
    bf16* __restrict__ oh, bf16* __restrict__ ol)
{
    extern __shared__ __align__(1024) char sm[];
    const uint32_t sQh = s2u(sm);
    const uint32_t sQl = sQh + 16384, sKh = sQh + 32768, sKl = sQh + 49152,
                   sVh = sQh + 65536, sVl = sQh + 81920;
    const int tid = threadIdx.x, w = tid >> 5, lane = tid & 31;
    const int q0 = blockIdx.x << 7;
    const int b  = blockIdx.y >> 4, h = blockIdx.y & 15;
    const size_t rbase = (size_t)b * SEQ;
    const int qoff = h * HD, koff = DM + h * HD, voff = 2 * DM + h * HD;

    const int lr  = lane & 15;
    const int lg  = lane >> 4;
    const int brr = (lane & 7) + ((lane & 16) >> 1);
    const int bg  = (lane >> 3) & 1;
    const int g4  = lane >> 2, l4 = lane & 3;
    const int qrow = w * 16 + lr;

    /* load Q tiles (hi & lo) */
#pragma unroll
    for (int it = 0; it < 4; it++) {
        int idx = tid + it * 256, rr = idx >> 3, g = idx & 7;
        size_t go = (rbase + q0 + rr) * QC + qoff + g * 8;
        int so = rr * 128 + ((g ^ (rr & 7)) << 4);
        *(uint4*)(sm + so)         = *(const uint4*)(qh + go);
        *(uint4*)(sm + 16384 + so) = *(const uint4*)(ql + go);
    }

    float o[8][4];
#pragma unroll
    for (int j = 0; j < 8; j++)
#pragma unroll
        for (int e = 0; e < 4; e++) o[j][e] = 0.f;
    float m0 = -1e30f, m1 = -1e30f, l0 = 0.f, l1 = 0.f;

#pragma unroll 1
    for (int kt = 0; kt < SEQ; kt += 128) {
        __syncthreads();
#pragma unroll
        for (int it = 0; it < 4; it++) {
            int idx = tid + it * 256, rr = idx >> 3, g = idx & 7;
            size_t go = (rbase + kt + rr) * QC + g * 8;
            int so = rr * 128 + ((g ^ (rr & 7)) << 4);
            *(uint4*)(sm + 32768 + so) = *(const uint4*)(qh + go + koff);
            *(uint4*)(sm + 49152 + so) = *(const uint4*)(ql + go + koff);
            *(uint4*)(sm + 65536 + so) = *(const uint4*)(qh + go + voff);
            *(uint4*)(sm + 81920 + so) = *(const uint4*)(ql + go + voff);
        }
        __syncthreads();

        /* ---- S = Q K^T (3 products) ---- */
        float s[16][4];
#pragma unroll
        for (int j = 0; j < 16; j++)
#pragma unroll
            for (int e = 0; e < 4; e++) s[j][e] = 0.f;

#pragma unroll
        for (int ks = 0; ks < 4; ks++) {
            uint32_t ah[4], al[4];
            int offA = qrow * 128 + (((2 * ks + lg) ^ (qrow & 7)) << 4);
            ldsm4(ah, sQh + offA);
            ldsm4(al, sQl + offA);
#pragma unroll
            for (int jp = 0; jp < 8; jp++) {
                int rb = jp * 16 + brr;
                int offB = rb * 128 + (((2 * ks + bg) ^ (rb & 7)) << 4);
                uint32_t bh4[4], bl4[4];
                ldsm4(bh4, sKh + offB);
                ldsm4(bl4, sKl + offB);
                mmabf(s[2 * jp],     ah, bh4[0], bh4[1]);
                mmabf(s[2 * jp],     ah, bl4[0], bl4[1]);
                mmabf(s[2 * jp],     al, bh4[0], bh4[1]);
                mmabf(s[2 * jp + 1], ah, bh4[2], bh4[3]);
                mmabf(s[2 * jp + 1], ah, bl4[2], bl4[3]);
                mmabf(s[2 * jp + 1], al, bh4[2], bh4[3]);
            }
        }

        /* ---- online softmax (base-2 domain, FMA-pipe exp2) ---- */
        float mx0 = -1e30f, mx1 = -1e30f;
#pragma unroll
        for (int j = 0; j < 16; j++) {
            mx0 = fmaxf(mx0, fmaxf(s[j][0], s[j][1]));
            mx1 = fmaxf(mx1, fmaxf(s[j][2], s[j][3]));
        }
        mx0 *= KSCL; mx1 *= KSCL;
#pragma unroll
        for (int ofs = 1; ofs <= 2; ofs <<= 1) {
            mx0 = fmaxf(mx0, __shfl_xor_sync(0xffffffffu, mx0, ofs));
            mx1 = fmaxf(mx1, __shfl_xor_sync(0xffffffffu, mx1, ofs));
        }
        float nm0 = fmaxf(m0, mx0), nm1 = fmaxf(m1, mx1);
        float a0 = exp2p(m0 - nm0), a1 = exp2p(m1 - nm1);
        m0 = nm0; m1 = nm1;

        float rs0 = 0.f, rs1 = 0.f;
#pragma unroll
        for (int j = 0; j < 16; j++) {
            s[j][0] = exp2p(fmaf(s[j][0], KSCL, -m0));
            s[j][1] = exp2p(fmaf(s[j][1], KSCL, -m0));
            s[j][2] = exp2p(fmaf(s[j][2], KSCL, -m1));
            s[j][3] = exp2p(fmaf(s[j][3], KSCL, -m1));
            rs0 += s[j][0] + s[j][1];
            rs1 += s[j][2] + s[j][3];
        }
#pragma unroll
        for (int ofs = 1; ofs <= 2; ofs <<= 1) {
            rs0 += __shfl_xor_sync(0xffffffffu, rs0, ofs);
            rs1 += __shfl_xor_sync(0xffffffffu, rs1, ofs);
        }
        l0 = l0 * a0 + rs0;
        l1 = l1 * a1 + rs1;
#pragma unroll
        for (int j = 0; j < 8; j++) {
            o[j][0] *= a0; o[j][1] *= a0;
            o[j][2] *= a1; o[j][3] *= a1;
        }

        /* ---- O += Ph*Vh + Pl*Vh + Ph*Vl (P split for precision) ---- */
#pragma unroll
        for (int ks = 0; ks < 8; ks++) {
            uint32_t pah[4], pal[4];
            split2(s[2 * ks][0],     s[2 * ks][1],     pah[0], pal[0]);
            split2(s[2 * ks][2],     s[2 * ks][3],     pah[1], pal[1]);
            split2(s[2 * ks + 1][0], s[2 * ks + 1][1], pah[2], pal[2]);
            split2(s[2 * ks + 1][2], s[2 * ks + 1][3], pah[3], pal[3]);
            int vr = ks * 16 + lr;
#pragma unroll
            for (int jp = 0; jp < 4; jp++) {
                int offV = vr * 128 + (((2 * jp + lg) ^ (vr & 7)) << 4);
                uint32_t vh4[4], vl4[4];
                ldsm4t(vh4, sVh + offV);
                ldsm4t(vl4, sVl + offV);
                mmabf(o[2 * jp],     pah, vh4[0], vh4[1]);
                mmabf(o[2 * jp],     pal, vh4[0], vh4[1]);
                mmabf(o[2 * jp],     pah, vl4[0], vl4[1]);
                mmabf(o[2 * jp + 1], pah, vh4[2], vh4[3]);
                mmabf(o[2 * jp + 1], pal, vh4[2], vh4[3]);
                mmabf(o[2 * jp + 1], pah, vl4[2], vl4[3]);
            }
        }
    }

    /* epilogue: normalize and write bf16 hi/lo */
    float i0 = 1.f / l0, i1 = 1.f / l1;
    size_t r0 = rbase + q0 + w * 16 + g4;
#pragma unroll
    for (int jn = 0; jn < 8; jn++) {
        int col = qoff + jn * 8 + l4 * 2;
        uint32_t hh, ll;
        split2(o[jn][0] * i0, o[jn][1] * i0, hh, ll);
        *(uint32_t*)(oh + r0 * DM + col) = hh;
        *(uint32_t*)(ol + r0 * DM + col) = ll;
        split2(o[jn][2] * i1, o[jn][3] * i1, hh, ll);
        *(uint32_t*)(oh + (r0 + 8) * DM + col) = hh;
        *(uint32_t*)(ol + (r0 + 8) * DM + col) = ll;
    }
}

/* ------------------------------------------------------------------ */
extern "C" void kernel_launch(void* const* d_in, const int* in_sizes, int n_in,
                              void* d_out, int out_size)
{
    (void)in_sizes; (void)n_in; (void)out_size;
    const float* x     = (const float*)d_in[0];
    const float* w_qkv = (const float*)d_in[1];
    const float* b_qkv = (const float*)d_in[2];
    const float* w_out = (const float*)d_in[3];
    const float* b_out = (const float*)d_in[4];
    float* out = (float*)d_out;

    bf16 *xh, *xl, *wqh, *wql, *woh, *wol, *qkvh, *qkvl, *ah, *al;
    cudaGetSymbolAddress((void**)&xh,   g_xh);
    cudaGetSymbolAddress((void**)&xl,   g_xl);
    cudaGetSymbolAddress((void**)&wqh,  g_wqh);
    cudaGetSymbolAddress((void**)&wql,  g_wql);
    cudaGetSymbolAddress((void**)&woh,  g_woh);
    cudaGetSymbolAddress((void**)&wol,  g_wol);
    cudaGetSymbolAddress((void**)&qkvh, g_qkvh);
    cudaGetSymbolAddress((void**)&qkvl, g_qkvl);
    cudaGetSymbolAddress((void**)&ah,   g_ah);
    cudaGetSymbolAddress((void**)&al,   g_al);

    cudaFuncSetAttribute(flash_mma_kernel,
                         cudaFuncAttributeMaxDynamicSharedMemorySize, FLASH_SMEM);
    cudaFuncSetAttribute(gemm_mma_kernel<1>,
                         cudaFuncAttributeMaxDynamicSharedMemorySize, GEMM_SMEM);
    cudaFuncSetAttribute(gemm_mma_kernel<0>,
                         cudaFuncAttributeMaxDynamicSharedMemorySize, GEMM_SMEM);

    /* 0) precision-split inputs + transposed weights */
    split_kernel<<<(ROWS * DM / 4 + 255) / 256, 256>>>(x, xh, xl, ROWS * DM / 4);
    transpose_split_kernel<<<dim3(QC / 32, DM / 32), dim3(32, 8)>>>(w_qkv, wqh, wql, QC);
    transpose_split_kernel<<<dim3(DM / 32, DM / 32), dim3(32, 8)>>>(w_out, woh, wol, DM);

    /* 1) QKV projection (writes bf16 hi/lo directly) */
    gemm_mma_kernel<1><<<dim3(QC / 128, ROWS / 128), 256, GEMM_SMEM>>>(
        xh, xl, wqh, wql, b_qkv, nullptr, qkvh, qkvl, QC);

    /* 2) flash attention (writes bf16 hi/lo) */
    flash_mma_kernel<<<dim3(SEQ / 128, BATCH * NH), 256, FLASH_SMEM>>>(
        qkvh, qkvl, ah, al);

    /* 3) output projection (writes fp32 final) */
    gemm_mma_kernel<0><<<dim3(DM / 128, ROWS / 128), 256, GEMM_SMEM>>>(
        ah, al, woh, wol, b_out, out, nullptr, nullptr, DM);
}

// round 7
// speedup vs baseline: 2.7573x; 1.2664x over previous
#include <cuda_runtime.h>
#include <cuda_bf16.h>
#include <stdint.h>

typedef __nv_bfloat16  bf16;
typedef __nv_bfloat162 bf162;

#define BATCH 4
#define SEQ   2048
#define DM    1024
#define NH    16
#define HD    64
#define ROWS  8192
#define QC    3072
/* 0.125 * log2(e) : softmax computed in base-2 domain */
#define KSCL  0.1803368801111204f

/* ---------------- scratch (__device__ globals) --------------------- */
__device__ bf16 g_xh[(size_t)ROWS * DM];
__device__ bf16 g_xl[(size_t)ROWS * DM];
__device__ bf16 g_wqh[(size_t)QC * DM];
__device__ bf16 g_wql[(size_t)QC * DM];
__device__ bf16 g_woh[(size_t)DM * DM];
__device__ bf16 g_wol[(size_t)DM * DM];
__device__ bf16 g_qkvh[(size_t)ROWS * QC];
__device__ bf16 g_qkvl[(size_t)ROWS * QC];
__device__ bf16 g_ah[(size_t)ROWS * DM];
__device__ bf16 g_al[(size_t)ROWS * DM];

/* ---------------- helpers ------------------------------------------ */
__device__ __forceinline__ uint32_t s2u(const void* p) {
    uint32_t a;
    asm("{ .reg .u64 t; cvta.to.shared.u64 t, %1; cvt.u32.u64 %0, t; }"
        : "=r"(a) : "l"(p));
    return a;
}
__device__ __forceinline__ void ldsm4(uint32_t* d, uint32_t a) {
    asm volatile("ldmatrix.sync.aligned.m8n8.x4.shared.b16 {%0,%1,%2,%3}, [%4];"
        : "=r"(d[0]), "=r"(d[1]), "=r"(d[2]), "=r"(d[3]) : "r"(a));
}
__device__ __forceinline__ void ldsm4t(uint32_t* d, uint32_t a) {
    asm volatile("ldmatrix.sync.aligned.m8n8.x4.trans.shared.b16 {%0,%1,%2,%3}, [%4];"
        : "=r"(d[0]), "=r"(d[1]), "=r"(d[2]), "=r"(d[3]) : "r"(a));
}
__device__ __forceinline__ void mmabf(float* c, const uint32_t* a,
                                      uint32_t b0, uint32_t b1) {
    asm volatile("mma.sync.aligned.m16n8k16.row.col.f32.bf16.bf16.f32 "
        "{%0,%1,%2,%3}, {%4,%5,%6,%7}, {%8,%9}, {%0,%1,%2,%3};"
        : "+f"(c[0]), "+f"(c[1]), "+f"(c[2]), "+f"(c[3])
        : "r"(a[0]), "r"(a[1]), "r"(a[2]), "r"(a[3]), "r"(b0), "r"(b1));
}
#define CP16(s, g) \
    asm volatile("cp.async.cg.shared.global [%0], [%1], 16;" :: "r"(s), "l"(g))
#define CPCOMMIT() asm volatile("cp.async.commit_group;" ::: "memory")
#define CPWAIT(n)  asm volatile("cp.async.wait_group %0;" :: "n"(n) : "memory")

/* exp2 on the FMA pipe (deg-5 poly around 0, |f|<=0.5, rel err ~2e-6) */
__device__ __forceinline__ float exp2p(float x) {
    x = fmaxf(x, -100.f);
    int i = __float2int_rn(x);
    float f = x - (float)i;
    float p = fmaf(1.3333558146e-3f, f, 9.6181291076e-3f);
    p = fmaf(p, f, 5.5504108664e-2f);
    p = fmaf(p, f, 2.4022650696e-1f);
    p = fmaf(p, f, 6.9314718056e-1f);
    p = fmaf(p, f, 1.0f);
    return p * __int_as_float((i + 127) << 23);
}
/* split (v0,v1) fp32 -> bf16x2 hi (round-nearest) + bf16x2 residual */
__device__ __forceinline__ void split2(float v0, float v1,
                                       uint32_t& hi, uint32_t& lo) {
    bf16 h0 = __float2bfloat16(v0), h1 = __float2bfloat16(v1);
    bf162 H; H.x = h0; H.y = h1;
    bf162 L;
    L.x = __float2bfloat16(v0 - __bfloat162float(h0));
    L.y = __float2bfloat16(v1 - __bfloat162float(h1));
    hi = *(uint32_t*)&H; lo = *(uint32_t*)&L;
}

/* ---------------- fp32 -> bf16 hi/lo split kernels ------------------ */
__global__ __launch_bounds__(256) void split_kernel(
    const float* __restrict__ in, bf16* __restrict__ hi,
    bf16* __restrict__ lo, int n4)
{
    int i = blockIdx.x * 256 + threadIdx.x;
    if (i >= n4) return;
    float4 v = ((const float4*)in)[i];
    uint32_t h0, l0, h1, l1;
    split2(v.x, v.y, h0, l0);
    split2(v.z, v.w, h1, l1);
    ((uint32_t*)hi)[2 * i] = h0; ((uint32_t*)hi)[2 * i + 1] = h1;
    ((uint32_t*)lo)[2 * i] = l0; ((uint32_t*)lo)[2 * i + 1] = l1;
}

/* w [1024, Ncols] fp32 -> wT hi/lo [Ncols, 1024] bf16 (K contiguous) */
__global__ __launch_bounds__(256) void transpose_split_kernel(
    const float* __restrict__ w, bf16* __restrict__ th,
    bf16* __restrict__ tl, int Ncols)
{
    __shared__ float t[32][33];
    int n0 = blockIdx.x * 32, k0 = blockIdx.y * 32;
    int tx = threadIdx.x, ty = threadIdx.y;   /* block (32,8) */
#pragma unroll
    for (int i = 0; i < 4; i++)
        t[ty + 8 * i][tx] = w[(size_t)(k0 + ty + 8 * i) * Ncols + n0 + tx];
    __syncthreads();
#pragma unroll
    for (int i = 0; i < 4; i++) {
        float v = t[tx][ty + 8 * i];
        bf16 h = __float2bfloat16(v);
        size_t o = (size_t)(n0 + ty + 8 * i) * DM + k0 + tx;
        th[o] = h;
        tl[o] = __float2bfloat16(v - __bfloat162float(h));
    }
}

/* ------------------------------------------------------------------ */
/* GEMM v2: C[M,N] = A[M,K] * B[N,K]^T + bias, 3-term bf16 split.      */
/* Block 256x128, warp tile 64x64 (8 warps 4x2), BK=32,                */
/* cp.async 3-stage pipeline, L2-only global path.                     */
/* ------------------------------------------------------------------ */
#define GSTG  49152                     /* bytes per stage */
#define GEMM_SMEM (3 * GSTG)            /* 144 KB */

template<int SPLIT_OUT>
__global__ __launch_bounds__(256, 1) void gemm_mma_kernel(
    const bf16* __restrict__ Ah, const bf16* __restrict__ Al,
    const bf16* __restrict__ Bh, const bf16* __restrict__ Bl,
    const float* __restrict__ bias, float* __restrict__ Cf,
    bf16* __restrict__ Ch, bf16* __restrict__ Cl, int N)
{
    extern __shared__ __align__(1024) char sm[];
    const uint32_t sb = s2u(sm);
    const int tid = threadIdx.x, w = tid >> 5, lane = tid & 31;
    const int wm = w >> 1, wn = w & 1;
    const int m0 = blockIdx.y << 8, n0 = blockIdx.x << 7;

    const int lr  = lane & 15;                       /* A-type ld row  */
    const int lg  = lane >> 4;                       /* A-type granule */
    const int brr = (lane & 7) + ((lane & 16) >> 1); /* B-type ld row  */
    const int bg  = (lane >> 3) & 1;                 /* B-type granule */
    const int g4  = lane >> 2, l4 = lane & 3;

    float c[4][8][4];
#pragma unroll
    for (int i = 0; i < 4; i++)
#pragma unroll
        for (int j = 0; j < 8; j++)
#pragma unroll
            for (int e = 0; e < 4; e++) c[i][j][e] = 0.f;

    /* cp.async one stage: Ah/Al 256x32, Bh/Bl 128x32, swizzled 64B rows */
    auto issue = [&](int stg, int k0) {
        uint32_t base = sb + stg * GSTG;
#pragma unroll
        for (int j = 0; j < 4; j++) {
            int idx = tid + j * 256, r = idx >> 2, g = idx & 3;
            uint32_t off = r * 64 + (((g ^ (r & 3))) << 4);
            size_t go = (size_t)(m0 + r) * DM + k0 + g * 8;
            CP16(base + off,          Ah + go);
            CP16(base + 16384 + off,  Al + go);
        }
#pragma unroll
        for (int j = 0; j < 2; j++) {
            int idx = tid + j * 256, r = idx >> 2, g = idx & 3;
            uint32_t off = r * 64 + (((g ^ (r & 3))) << 4);
            size_t go = (size_t)(n0 + r) * DM + k0 + g * 8;
            CP16(base + 32768 + off,  Bh + go);
            CP16(base + 40960 + off,  Bl + go);
        }
        CPCOMMIT();
    };

    issue(0, 0); issue(1, 32); issue(2, 64);

#pragma unroll 1
    for (int s = 0; s < 32; s++) {
        CPWAIT(2);
        __syncthreads();
        uint32_t base = sb + (s % 3) * GSTG;
#pragma unroll
        for (int ks = 0; ks < 2; ks++) {
            uint32_t ah[4][4], al[4][4];
#pragma unroll
            for (int im = 0; im < 4; im++) {
                int ar = wm * 64 + im * 16 + lr;
                uint32_t offA = ar * 64 + (((2 * ks + lg) ^ (ar & 3)) << 4);
                ldsm4(ah[im], base + offA);
                ldsm4(al[im], base + 16384 + offA);
            }
#pragma unroll
            for (int jp = 0; jp < 4; jp++) {
                int rb = wn * 64 + jp * 16 + brr;
                uint32_t offB = rb * 64 + (((2 * ks + bg) ^ (rb & 3)) << 4);
                uint32_t bh4[4], bl4[4];
                ldsm4(bh4, base + 32768 + offB);
                ldsm4(bl4, base + 40960 + offB);
#pragma unroll
                for (int im = 0; im < 4; im++) {
                    mmabf(c[im][2 * jp],     ah[im], bh4[0], bh4[1]);
                    mmabf(c[im][2 * jp],     ah[im], bl4[0], bl4[1]);
                    mmabf(c[im][2 * jp],     al[im], bh4[0], bh4[1]);
                    mmabf(c[im][2 * jp + 1], ah[im], bh4[2], bh4[3]);
                    mmabf(c[im][2 * jp + 1], ah[im], bl4[2], bl4[3]);
                    mmabf(c[im][2 * jp + 1], al[im], bh4[2], bh4[3]);
                }
            }
        }
        __syncthreads();
        if (s + 3 < 32) issue(s % 3, (s + 3) * 32);
    }

    /* epilogue */
#pragma unroll
    for (int im = 0; im < 4; im++) {
#pragma unroll
        for (int jn = 0; jn < 8; jn++) {
            int row = m0 + wm * 64 + im * 16 + g4;
            int col = n0 + wn * 64 + jn * 8 + l4 * 2;
            float2 bb = *(const float2*)(bias + col);
            float v0 = c[im][jn][0] + bb.x, v1 = c[im][jn][1] + bb.y;
            float v2 = c[im][jn][2] + bb.x, v3 = c[im][jn][3] + bb.y;
            if (SPLIT_OUT) {
                uint32_t h, l;
                split2(v0, v1, h, l);
                *(uint32_t*)(Ch + (size_t)row * N + col) = h;
                *(uint32_t*)(Cl + (size_t)row * N + col) = l;
                split2(v2, v3, h, l);
                *(uint32_t*)(Ch + (size_t)(row + 8) * N + col) = h;
                *(uint32_t*)(Cl + (size_t)(row + 8) * N + col) = l;
            } else {
                *(float2*)(Cf + (size_t)row * N + col)       = make_float2(v0, v1);
                *(float2*)(Cf + (size_t)(row + 8) * N + col) = make_float2(v2, v3);
            }
        }
    }
}

/* ------------------------------------------------------------------ */
/* Flash attention, FA2-style on mma.sync. BM=BN=128, 8 warps x 16 rows*/
/* S: 3-term split; P: 2-term split; KV double-buffered via cp.async.  */
/* ------------------------------------------------------------------ */
#define KVSTG 65536
#define FLASH_SMEM (32768 + 2 * KVSTG)   /* 160 KB */

__global__ __launch_bounds__(256, 1) void flash_mma_kernel(
    const bf16* __restrict__ qh, const bf16* __restrict__ ql,
    bf16* __restrict__ oh, bf16* __restrict__ ol)
{
    extern __shared__ __align__(1024) char sm[];
    const uint32_t sQh = s2u(sm);
    const uint32_t sQl = sQh + 16384;
    const int tid = threadIdx.x, w = tid >> 5, lane = tid & 31;
    const int q0 = blockIdx.x << 7;
    const int b  = blockIdx.y >> 4, h = blockIdx.y & 15;
    const size_t rbase = (size_t)b * SEQ;
    const int qoff = h * HD, koff = DM + h * HD, voff = 2 * DM + h * HD;

    const int lr  = lane & 15;
    const int lg  = lane >> 4;
    const int brr = (lane & 7) + ((lane & 16) >> 1);
    const int bg  = (lane >> 3) & 1;
    const int g4  = lane >> 2, l4 = lane & 3;
    const int qrow = w * 16 + lr;

    /* cp.async one KV stage (Kh,Kl,Vh,Vl: 128x64 each, 128B rows) */
    auto kvload = [&](int stg, int kt) {
        uint32_t base = sQh + 32768 + stg * KVSTG;
#pragma unroll
        for (int j = 0; j < 4; j++) {
            int idx = tid + j * 256, rr = idx >> 3, g = idx & 7;
            size_t go = (rbase + kt + rr) * QC + g * 8;
            uint32_t off = rr * 128 + ((g ^ (rr & 7)) << 4);
            CP16(base + off,          qh + go + koff);
            CP16(base + 16384 + off,  ql + go + koff);
            CP16(base + 32768 + off,  qh + go + voff);
            CP16(base + 49152 + off,  ql + go + voff);
        }
        CPCOMMIT();
    };

    /* load Q tiles (hi & lo) */
#pragma unroll
    for (int it = 0; it < 4; it++) {
        int idx = tid + it * 256, rr = idx >> 3, g = idx & 7;
        size_t go = (rbase + q0 + rr) * QC + qoff + g * 8;
        int so = rr * 128 + ((g ^ (rr & 7)) << 4);
        *(uint4*)(sm + so)         = *(const uint4*)(qh + go);
        *(uint4*)(sm + 16384 + so) = *(const uint4*)(ql + go);
    }
    kvload(0, 0);
    kvload(1, 128);

    float o[8][4];
#pragma unroll
    for (int j = 0; j < 8; j++)
#pragma unroll
        for (int e = 0; e < 4; e++) o[j][e] = 0.f;
    float m0 = -1e30f, m1 = -1e30f, l0 = 0.f, l1 = 0.f;

#pragma unroll 1
    for (int it = 0; it < SEQ / 128; it++) {
        CPWAIT(1);
        __syncthreads();
        const uint32_t sKh = sQh + 32768 + (it & 1) * KVSTG;
        const uint32_t sKl = sKh + 16384, sVh = sKh + 32768, sVl = sKh + 49152;

        /* ---- S = Q K^T (3 products) ---- */
        float s[16][4];
#pragma unroll
        for (int j = 0; j < 16; j++)
#pragma unroll
            for (int e = 0; e < 4; e++) s[j][e] = 0.f;

#pragma unroll
        for (int ks = 0; ks < 4; ks++) {
            uint32_t ah[4], al[4];
            int offA = qrow * 128 + (((2 * ks + lg) ^ (qrow & 7)) << 4);
            ldsm4(ah, sQh + offA);
            ldsm4(al, sQl + offA);
#pragma unroll
            for (int jp = 0; jp < 8; jp++) {
                int rb = jp * 16 + brr;
                int offB = rb * 128 + (((2 * ks + bg) ^ (rb & 7)) << 4);
                uint32_t bh4[4], bl4[4];
                ldsm4(bh4, sKh + offB);
                ldsm4(bl4, sKl + offB);
                mmabf(s[2 * jp],     ah, bh4[0], bh4[1]);
                mmabf(s[2 * jp],     ah, bl4[0], bl4[1]);
                mmabf(s[2 * jp],     al, bh4[0], bh4[1]);
                mmabf(s[2 * jp + 1], ah, bh4[2], bh4[3]);
                mmabf(s[2 * jp + 1], ah, bl4[2], bl4[3]);
                mmabf(s[2 * jp + 1], al, bh4[2], bh4[3]);
            }
        }

        /* ---- online softmax (base-2 domain, FMA-pipe exp2) ---- */
        float mx0 = -1e30f, mx1 = -1e30f;
#pragma unroll
        for (int j = 0; j < 16; j++) {
            mx0 = fmaxf(mx0, fmaxf(s[j][0], s[j][1]));
            mx1 = fmaxf(mx1, fmaxf(s[j][2], s[j][3]));
        }
        mx0 *= KSCL; mx1 *= KSCL;
#pragma unroll
        for (int ofs = 1; ofs <= 2; ofs <<= 1) {
            mx0 = fmaxf(mx0, __shfl_xor_sync(0xffffffffu, mx0, ofs));
            mx1 = fmaxf(mx1, __shfl_xor_sync(0xffffffffu, mx1, ofs));
        }
        float nm0 = fmaxf(m0, mx0), nm1 = fmaxf(m1, mx1);
        float a0 = exp2p(m0 - nm0), a1 = exp2p(m1 - nm1);
        m0 = nm0; m1 = nm1;

        float rs0 = 0.f, rs1 = 0.f;
#pragma unroll
        for (int j = 0; j < 16; j++) {
            s[j][0] = exp2p(fmaf(s[j][0], KSCL, -m0));
            s[j][1] = exp2p(fmaf(s[j][1], KSCL, -m0));
            s[j][2] = exp2p(fmaf(s[j][2], KSCL, -m1));
            s[j][3] = exp2p(fmaf(s[j][3], KSCL, -m1));
            rs0 += s[j][0] + s[j][1];
            rs1 += s[j][2] + s[j][3];
        }
#pragma unroll
        for (int ofs = 1; ofs <= 2; ofs <<= 1) {
            rs0 += __shfl_xor_sync(0xffffffffu, rs0, ofs);
            rs1 += __shfl_xor_sync(0xffffffffu, rs1, ofs);
        }
        l0 = l0 * a0 + rs0;
        l1 = l1 * a1 + rs1;
#pragma unroll
        for (int j = 0; j < 8; j++) {
            o[j][0] *= a0; o[j][1] *= a0;
            o[j][2] *= a1; o[j][3] *= a1;
        }

        /* ---- O += Ph*Vh + Pl*Vh + Ph*Vl (P split for precision) ---- */
#pragma unroll
        for (int ks = 0; ks < 8; ks++) {
            uint32_t pah[4], pal[4];
            split2(s[2 * ks][0],     s[2 * ks][1],     pah[0], pal[0]);
            split2(s[2 * ks][2],     s[2 * ks][3],     pah[1], pal[1]);
            split2(s[2 * ks + 1][0], s[2 * ks + 1][1], pah[2], pal[2]);
            split2(s[2 * ks + 1][2], s[2 * ks + 1][3], pah[3], pal[3]);
            int vr = ks * 16 + lr;
#pragma unroll
            for (int jp = 0; jp < 4; jp++) {
                int offV = vr * 128 + (((2 * jp + lg) ^ (vr & 7)) << 4);
                uint32_t vh4[4], vl4[4];
                ldsm4t(vh4, sVh + offV);
                ldsm4t(vl4, sVl + offV);
                mmabf(o[2 * jp],     pah, vh4[0], vh4[1]);
                mmabf(o[2 * jp],     pal, vh4[0], vh4[1]);
                mmabf(o[2 * jp],     pah, vl4[0], vl4[1]);
                mmabf(o[2 * jp + 1], pah, vh4[2], vh4[3]);
                mmabf(o[2 * jp + 1], pal, vh4[2], vh4[3]);
                mmabf(o[2 * jp + 1], pah, vl4[2], vl4[3]);
            }
        }
        __syncthreads();
        if (it + 2 < SEQ / 128) kvload(it & 1, (it + 2) * 128);
    }

    /* epilogue: normalize and write bf16 hi/lo */
    float i0 = 1.f / l0, i1 = 1.f / l1;
    size_t r0 = rbase + q0 + w * 16 + g4;
#pragma unroll
    for (int jn = 0; jn < 8; jn++) {
        int col = qoff + jn * 8 + l4 * 2;
        uint32_t hh, ll;
        split2(o[jn][0] * i0, o[jn][1] * i0, hh, ll);
        *(uint32_t*)(oh + r0 * DM + col) = hh;
        *(uint32_t*)(ol + r0 * DM + col) = ll;
        split2(o[jn][2] * i1, o[jn][3] * i1, hh, ll);
        *(uint32_t*)(oh + (r0 + 8) * DM + col) = hh;
        *(uint32_t*)(ol + (r0 + 8) * DM + col) = ll;
    }
}

/* ------------------------------------------------------------------ */
extern "C" void kernel_launch(void* const* d_in, const int* in_sizes, int n_in,
                              void* d_out, int out_size)
{
    (void)in_sizes; (void)n_in; (void)out_size;
    const float* x     = (const float*)d_in[0];
    const float* w_qkv = (const float*)d_in[1];
    const float* b_qkv = (const float*)d_in[2];
    const float* w_out = (const float*)d_in[3];
    const float* b_out = (const float*)d_in[4];
    float* out = (float*)d_out;

    bf16 *xh, *xl, *wqh, *wql, *woh, *wol, *qkvh, *qkvl, *ah, *al;
    cudaGetSymbolAddress((void**)&xh,   g_xh);
    cudaGetSymbolAddress((void**)&xl,   g_xl);
    cudaGetSymbolAddress((void**)&wqh,  g_wqh);
    cudaGetSymbolAddress((void**)&wql,  g_wql);
    cudaGetSymbolAddress((void**)&woh,  g_woh);
    cudaGetSymbolAddress((void**)&wol,  g_wol);
    cudaGetSymbolAddress((void**)&qkvh, g_qkvh);
    cudaGetSymbolAddress((void**)&qkvl, g_qkvl);
    cudaGetSymbolAddress((void**)&ah,   g_ah);
    cudaGetSymbolAddress((void**)&al,   g_al);

    cudaFuncSetAttribute(flash_mma_kernel,
                         cudaFuncAttributeMaxDynamicSharedMemorySize, FLASH_SMEM);
    cudaFuncSetAttribute(gemm_mma_kernel<1>,
                         cudaFuncAttributeMaxDynamicSharedMemorySize, GEMM_SMEM);
    cudaFuncSetAttribute(gemm_mma_kernel<0>,
                         cudaFuncAttributeMaxDynamicSharedMemorySize, GEMM_SMEM);

    /* 0) precision-split inputs + transposed weights */
    split_kernel<<<(ROWS * DM / 4 + 255) / 256, 256>>>(x, xh, xl, ROWS * DM / 4);
    transpose_split_kernel<<<dim3(QC / 32, DM / 32), dim3(32, 8)>>>(w_qkv, wqh, wql, QC);
    transpose_split_kernel<<<dim3(DM / 32, DM / 32), dim3(32, 8)>>>(w_out, woh, wol, DM);

    /* 1) QKV projection (writes bf16 hi/lo directly) */
    gemm_mma_kernel<1><<<dim3(QC / 128, ROWS / 256), 256, GEMM_SMEM>>>(
        xh, xl, wqh, wql, b_qkv, nullptr, qkvh, qkvl, QC);

    /* 2) flash attention (writes bf16 hi/lo) */
    flash_mma_kernel<<<dim3(SEQ / 128, BATCH * NH), 256, FLASH_SMEM>>>(
        qkvh, qkvl, ah, al);

    /* 3) output projection (writes fp32 final) */
    gemm_mma_kernel<0><<<dim3(DM / 128, ROWS / 256), 256, GEMM_SMEM>>>(
        ah, al, woh, wol, b_out, out, nullptr, nullptr, DM);
}

// round 9
// speedup vs baseline: 2.7612x; 1.0014x over previous
#include <cuda_runtime.h>
#include <cuda_bf16.h>
#include <stdint.h>

typedef __nv_bfloat16  bf16;
typedef __nv_bfloat162 bf162;

#define BATCH 4
#define SEQ   2048
#define DM    1024
#define NH    16
#define HD    64
#define ROWS  8192
#define QC    3072
/* 0.125 * log2(e) : softmax computed in base-2 domain */
#define KSCL  0.1803368801111204f

/* ---------------- scratch (__device__ globals) --------------------- */
__device__ bf16 g_xh[(size_t)ROWS * DM];
__device__ bf16 g_xl[(size_t)ROWS * DM];
__device__ bf16 g_wqh[(size_t)QC * DM];
__device__ bf16 g_wql[(size_t)QC * DM];
__device__ bf16 g_woh[(size_t)DM * DM];
__device__ bf16 g_wol[(size_t)DM * DM];
__device__ bf16 g_qkvh[(size_t)ROWS * QC];
__device__ bf16 g_qkvl[(size_t)ROWS * QC];
__device__ bf16 g_ah[(size_t)ROWS * DM];
__device__ bf16 g_al[(size_t)ROWS * DM];

/* ---------------- helpers ------------------------------------------ */
__device__ __forceinline__ uint32_t s2u(const void* p) {
    uint32_t a;
    asm("{ .reg .u64 t; cvta.to.shared.u64 t, %1; cvt.u32.u64 %0, t; }"
        : "=r"(a) : "l"(p));
    return a;
}
__device__ __forceinline__ void ldsm4(uint32_t* d, uint32_t a) {
    asm volatile("ldmatrix.sync.aligned.m8n8.x4.shared.b16 {%0,%1,%2,%3}, [%4];"
        : "=r"(d[0]), "=r"(d[1]), "=r"(d[2]), "=r"(d[3]) : "r"(a));
}
__device__ __forceinline__ void ldsm4t(uint32_t* d, uint32_t a) {
    asm volatile("ldmatrix.sync.aligned.m8n8.x4.trans.shared.b16 {%0,%1,%2,%3}, [%4];"
        : "=r"(d[0]), "=r"(d[1]), "=r"(d[2]), "=r"(d[3]) : "r"(a));
}
__device__ __forceinline__ void mmabf(float* c, const uint32_t* a,
                                      uint32_t b0, uint32_t b1) {
    asm volatile("mma.sync.aligned.m16n8k16.row.col.f32.bf16.bf16.f32 "
        "{%0,%1,%2,%3}, {%4,%5,%6,%7}, {%8,%9}, {%0,%1,%2,%3};"
        : "+f"(c[0]), "+f"(c[1]), "+f"(c[2]), "+f"(c[3])
        : "r"(a[0]), "r"(a[1]), "r"(a[2]), "r"(a[3]), "r"(b0), "r"(b1));
}
#define CP16(s, g) \
    asm volatile("cp.async.cg.shared.global [%0], [%1], 16;" :: "r"(s), "l"(g))
#define CPCOMMIT() asm volatile("cp.async.commit_group;" ::: "memory")
#define CPWAIT(n)  asm volatile("cp.async.wait_group %0;" :: "n"(n) : "memory")

/* exp2 on the FMA pipe (deg-5 poly around 0, |f|<=0.5, rel err ~2e-6) */
__device__ __forceinline__ float exp2p(float x) {
    x = fmaxf(x, -100.f);
    int i = __float2int_rn(x);
    float f = x - (float)i;
    float p = fmaf(1.3333558146e-3f, f, 9.6181291076e-3f);
    p = fmaf(p, f, 5.5504108664e-2f);
    p = fmaf(p, f, 2.4022650696e-1f);
    p = fmaf(p, f, 6.9314718056e-1f);
    p = fmaf(p, f, 1.0f);
    return p * __int_as_float((i + 127) << 23);
}
/* split (v0,v1) fp32 -> bf16x2 hi (round-nearest) + bf16x2 residual */
__device__ __forceinline__ void split2(float v0, float v1,
                                       uint32_t& hi, uint32_t& lo) {
    bf16 h0 = __float2bfloat16(v0), h1 = __float2bfloat16(v1);
    bf162 H; H.x = h0; H.y = h1;
    bf162 L;
    L.x = __float2bfloat16(v0 - __bfloat162float(h0));
    L.y = __float2bfloat16(v1 - __bfloat162float(h1));
    hi = *(uint32_t*)&H; lo = *(uint32_t*)&L;
}

/* ---------------- fp32 -> bf16 hi/lo split kernels ------------------ */
__global__ __launch_bounds__(256) void split_kernel(
    const float* __restrict__ in, bf16* __restrict__ hi,
    bf16* __restrict__ lo, int n4)
{
    int i = blockIdx.x * 256 + threadIdx.x;
    if (i >= n4) return;
    float4 v = ((const float4*)in)[i];
    uint32_t h0, l0, h1, l1;
    split2(v.x, v.y, h0, l0);
    split2(v.z, v.w, h1, l1);
    ((uint32_t*)hi)[2 * i] = h0; ((uint32_t*)hi)[2 * i + 1] = h1;
    ((uint32_t*)lo)[2 * i] = l0; ((uint32_t*)lo)[2 * i + 1] = l1;
}

/* w [1024, Ncols] fp32 -> wT hi/lo [Ncols, 1024] bf16 (K contiguous) */
__global__ __launch_bounds__(256) void transpose_split_kernel(
    const float* __restrict__ w, bf16* __restrict__ th,
    bf16* __restrict__ tl, int Ncols)
{
    __shared__ float t[32][33];
    int n0 = blockIdx.x * 32, k0 = blockIdx.y * 32;
    int tx = threadIdx.x, ty = threadIdx.y;   /* block (32,8) */
#pragma unroll
    for (int i = 0; i < 4; i++)
        t[ty + 8 * i][tx] = w[(size_t)(k0 + ty + 8 * i) * Ncols + n0 + tx];
    __syncthreads();
#pragma unroll
    for (int i = 0; i < 4; i++) {
        float v = t[tx][ty + 8 * i];
        bf16 h = __float2bfloat16(v);
        size_t o = (size_t)(n0 + ty + 8 * i) * DM + k0 + tx;
        th[o] = h;
        tl[o] = __float2bfloat16(v - __bfloat162float(h));
    }
}

/* ------------------------------------------------------------------ */
/* GEMM: C[M,N] = A[M,K] * B[N,K]^T + bias, 3-term bf16 split.         */
/* Block 256x128, warp tile 64x64, BK=32, cp.async 3-stage pipeline.   */
/* MMA issue order: term-outer / im-inner (dep distance 8).            */
/* ------------------------------------------------------------------ */
#define GSTG  49152                     /* bytes per stage */
#define GEMM_SMEM (3 * GSTG)            /* 144 KB */

template<int SPLIT_OUT>
__global__ __launch_bounds__(256, 1) void gemm_mma_kernel(
    const bf16* __restrict__ Ah, const bf16* __restrict__ Al,
    const bf16* __restrict__ Bh, const bf16* __restrict__ Bl,
    const float* __restrict__ bias, float* __restrict__ Cf,
    bf16* __restrict__ Ch, bf16* __restrict__ Cl, int N)
{
    extern __shared__ __align__(1024) char sm[];
    const uint32_t sb = s2u(sm);
    const int tid = threadIdx.x, w = tid >> 5, lane = tid & 31;
    const int wm = w >> 1, wn = w & 1;
    const int m0 = blockIdx.y << 8, n0 = blockIdx.x << 7;

    const int lr  = lane & 15;                       /* A-type ld row  */
    const int lg  = lane >> 4;                       /* A-type granule */
    const int brr = (lane & 7) + ((lane & 16) >> 1); /* B-type ld row  */
    const int bg  = (lane >> 3) & 1;                 /* B-type granule */
    const int g4  = lane >> 2, l4 = lane & 3;

    float c[4][8][4];
#pragma unroll
    for (int i = 0; i < 4; i++)
#pragma unroll
        for (int j = 0; j < 8; j++)
#pragma unroll
            for (int e = 0; e < 4; e++) c[i][j][e] = 0.f;

    /* cp.async one stage: Ah/Al 256x32, Bh/Bl 128x32, swizzled 64B rows */
    auto issue = [&](int stg, int k0) {
        uint32_t base = sb + stg * GSTG;
#pragma unroll
        for (int j = 0; j < 4; j++) {
            int idx = tid + j * 256, r = idx >> 2, g = idx & 3;
            uint32_t off = r * 64 + (((g ^ (r & 3))) << 4);
            size_t go = (size_t)(m0 + r) * DM + k0 + g * 8;
            CP16(base + off,          Ah + go);
            CP16(base + 16384 + off,  Al + go);
        }
#pragma unroll
        for (int j = 0; j < 2; j++) {
            int idx = tid + j * 256, r = idx >> 2, g = idx & 3;
            uint32_t off = r * 64 + (((g ^ (r & 3))) << 4);
            size_t go = (size_t)(n0 + r) * DM + k0 + g * 8;
            CP16(base + 32768 + off,  Bh + go);
            CP16(base + 40960 + off,  Bl + go);
        }
        CPCOMMIT();
    };

    issue(0, 0); issue(1, 32); issue(2, 64);

#pragma unroll 1
    for (int s = 0; s < 32; s++) {
        CPWAIT(2);
        __syncthreads();
        uint32_t base = sb + (s % 3) * GSTG;
#pragma unroll
        for (int ks = 0; ks < 2; ks++) {
            uint32_t ah[4][4], al[4][4];
#pragma unroll
            for (int im = 0; im < 4; im++) {
                int ar = wm * 64 + im * 16 + lr;
                uint32_t offA = ar * 64 + (((2 * ks + lg) ^ (ar & 3)) << 4);
                ldsm4(ah[im], base + offA);
                ldsm4(al[im], base + 16384 + offA);
            }
#pragma unroll
            for (int jp = 0; jp < 4; jp++) {
                int rb = wn * 64 + jp * 16 + brr;
                uint32_t offB = rb * 64 + (((2 * ks + bg) ^ (rb & 3)) << 4);
                uint32_t bh4[4], bl4[4];
                ldsm4(bh4, base + 32768 + offB);
                ldsm4(bl4, base + 40960 + offB);
                /* term-outer, im-inner: dep distance 8 per accumulator */
#pragma unroll
                for (int im = 0; im < 4; im++)
                    mmabf(c[im][2 * jp],     ah[im], bh4[0], bh4[1]);
#pragma unroll
                for (int im = 0; im < 4; im++)
                    mmabf(c[im][2 * jp + 1], ah[im], bh4[2], bh4[3]);
#pragma unroll
                for (int im = 0; im < 4; im++)
                    mmabf(c[im][2 * jp],     ah[im], bl4[0], bl4[1]);
#pragma unroll
                for (int im = 0; im < 4; im++)
                    mmabf(c[im][2 * jp + 1], ah[im], bl4[2], bl4[3]);
#pragma unroll
                for (int im = 0; im < 4; im++)
                    mmabf(c[im][2 * jp],     al[im], bh4[0], bh4[1]);
#pragma unroll
                for (int im = 0; im < 4; im++)
                    mmabf(c[im][2 * jp + 1], al[im], bh4[2], bh4[3]);
            }
        }
        __syncthreads();
        if (s + 3 < 32) issue(s % 3, (s + 3) * 32);
    }

    /* epilogue */
#pragma unroll
    for (int im = 0; im < 4; im++) {
#pragma unroll
        for (int jn = 0; jn < 8; jn++) {
            int row = m0 + wm * 64 + im * 16 + g4;
            int col = n0 + wn * 64 + jn * 8 + l4 * 2;
            float2 bb = *(const float2*)(bias + col);
            float v0 = c[im][jn][0] + bb.x, v1 = c[im][jn][1] + bb.y;
            float v2 = c[im][jn][2] + bb.x, v3 = c[im][jn][3] + bb.y;
            if (SPLIT_OUT) {
                uint32_t h, l;
                split2(v0, v1, h, l);
                *(uint32_t*)(Ch + (size_t)row * N + col) = h;
                *(uint32_t*)(Cl + (size_t)row * N + col) = l;
                split2(v2, v3, h, l);
                *(uint32_t*)(Ch + (size_t)(row + 8) * N + col) = h;
                *(uint32_t*)(Cl + (size_t)(row + 8) * N + col) = l;
            } else {
                *(float2*)(Cf + (size_t)row * N + col)       = make_float2(v0, v1);
                *(float2*)(Cf + (size_t)(row + 8) * N + col) = make_float2(v2, v3);
            }
        }
    }
}

/* ------------------------------------------------------------------ */
/* Flash attention, FA2-style on mma.sync. BM=BN=128, 8 warps x 16 rows*/
/* S: 3-term split; P: 2-term split; KV double-buffered via cp.async.  */
/* MMA issue rotates across 4 accumulators (dep distance 4).           */
/* ------------------------------------------------------------------ */
#define KVSTG 65536
#define FLASH_SMEM (32768 + 2 * KVSTG)   /* 160 KB */

__global__ __launch_bounds__(256, 1) void flash_mma_kernel(
    const bf16* __restrict__ qh, const bf16* __restrict__ ql,
    bf16* __restrict__ oh, bf16* __restrict__ ol)
{
    extern __shared__ __align__(1024) char sm[];
    const uint32_t sQh = s2u(sm);
    const uint32_t sQl = sQh + 16384;
    const int tid = threadIdx.x, w = tid >> 5, lane = tid & 31;
    const int q0 = blockIdx.x << 7;
    const int b  = blockIdx.y >> 4, h = blockIdx.y & 15;
    const size_t rbase = (size_t)b * SEQ;
    const int qoff = h * HD, koff = DM + h * HD, voff = 2 * DM + h * HD;

    const int lr  = lane & 15;
    const int lg  = lane >> 4;
    const int brr = (lane & 7) + ((lane & 16) >> 1);
    const int bg  = (lane >> 3) & 1;
    const int g4  = lane >> 2, l4 = lane & 3;
    const int qrow = w * 16 + lr;

    /* cp.async one KV stage (Kh,Kl,Vh,Vl: 128x64 each, 128B rows) */
    auto kvload = [&](int stg, int kt) {
        uint32_t base = sQh + 32768 + stg * KVSTG;
#pragma unroll
        for (int j = 0; j < 4; j++) {
            int idx = tid + j * 256, rr = idx >> 3, g = idx & 7;
            size_t go = (rbase + kt + rr) * QC + g * 8;
            uint32_t off = rr * 128 + ((g ^ (rr & 7)) << 4);
            CP16(base + off,          qh + go + koff);
            CP16(base + 16384 + off,  ql + go + koff);
            CP16(base + 32768 + off,  qh + go + voff);
            CP16(base + 49152 + off,  ql + go + voff);
        }
        CPCOMMIT();
    };

    /* load Q tiles (hi & lo) */
#pragma unroll
    for (int it = 0; it < 4; it++) {
        int idx = tid + it * 256, rr = idx >> 3, g = idx & 7;
        size_t go = (rbase + q0 + rr) * QC + qoff + g * 8;
        int so = rr * 128 + ((g ^ (rr & 7)) << 4);
        *(uint4*)(sm + so)         = *(const uint4*)(qh + go);
        *(uint4*)(sm + 16384 + so) = *(const uint4*)(ql + go);
    }
    kvload(0, 0);
    kvload(1, 128);

    float o[8][4];
#pragma unroll
    for (int j = 0; j < 8; j++)
#pragma unroll
        for (int e = 0; e < 4; e++) o[j][e] = 0.f;
    float m0 = -1e30f, m1 = -1e30f, l0 = 0.f, l1 = 0.f;

#pragma unroll 1
    for (int it = 0; it < SEQ / 128; it++) {
        CPWAIT(1);
        __syncthreads();
        const uint32_t sKh = sQh + 32768 + (it & 1) * KVSTG;
        const uint32_t sKl = sKh + 16384, sVh = sKh + 32768, sVl = sKh + 49152;

        /* ---- S = Q K^T (3 products), K-rows in pairs: 4-acc rotation */
        float s[16][4];
#pragma unroll
        for (int j = 0; j < 16; j++)
#pragma unroll
            for (int e = 0; e < 4; e++) s[j][e] = 0.f;

#pragma unroll
        for (int ks = 0; ks < 4; ks++) {
            uint32_t ah[4], al[4];
            int offA = qrow * 128 + (((2 * ks + lg) ^ (qrow & 7)) << 4);
            ldsm4(ah, sQh + offA);
            ldsm4(al, sQl + offA);
#pragma unroll
            for (int jpp = 0; jpp < 4; jpp++) {
                int rb0 = (2 * jpp) * 16 + brr;
                int rb1 = (2 * jpp + 1) * 16 + brr;
                int offB0 = rb0 * 128 + (((2 * ks + bg) ^ (rb0 & 7)) << 4);
                int offB1 = rb1 * 128 + (((2 * ks + bg) ^ (rb1 & 7)) << 4);
                uint32_t bhA[4], blA[4], bhB[4], blB[4];
                ldsm4(bhA, sKh + offB0);
                ldsm4(blA, sKl + offB0);
                ldsm4(bhB, sKh + offB1);
                ldsm4(blB, sKl + offB1);
                float* s0 = s[4 * jpp];     float* s1 = s[4 * jpp + 1];
                float* s2 = s[4 * jpp + 2]; float* s3 = s[4 * jpp + 3];
                mmabf(s0, ah, bhA[0], bhA[1]);
                mmabf(s1, ah, bhA[2], bhA[3]);
                mmabf(s2, ah, bhB[0], bhB[1]);
                mmabf(s3, ah, bhB[2], bhB[3]);
                mmabf(s0, ah, blA[0], blA[1]);
                mmabf(s1, ah, blA[2], blA[3]);
                mmabf(s2, ah, blB[0], blB[1]);
                mmabf(s3, ah, blB[2], blB[3]);
                mmabf(s0, al, bhA[0], bhA[1]);
                mmabf(s1, al, bhA[2], bhA[3]);
                mmabf(s2, al, bhB[0], bhB[1]);
                mmabf(s3, al, bhB[2], bhB[3]);
            }
        }

        /* ---- online softmax (base-2 domain, FMA-pipe exp2) ---- */
        float mx0 = -1e30f, mx1 = -1e30f;
#pragma unroll
        for (int j = 0; j < 16; j++) {
            mx0 = fmaxf(mx0, fmaxf(s[j][0], s[j][1]));
            mx1 = fmaxf(mx1, fmaxf(s[j][2], s[j][3]));
        }
        mx0 *= KSCL; mx1 *= KSCL;
#pragma unroll
        for (int ofs = 1; ofs <= 2; ofs <<= 1) {
            mx0 = fmaxf(mx0, __shfl_xor_sync(0xffffffffu, mx0, ofs));
            mx1 = fmaxf(mx1, __shfl_xor_sync(0xffffffffu, mx1, ofs));
        }
        float nm0 = fmaxf(m0, mx0), nm1 = fmaxf(m1, mx1);
        float a0 = exp2p(m0 - nm0), a1 = exp2p(m1 - nm1);
        m0 = nm0; m1 = nm1;

        float rs0 = 0.f, rs1 = 0.f;
#pragma unroll
        for (int j = 0; j < 16; j++) {
            s[j][0] = exp2p(fmaf(s[j][0], KSCL, -m0));
            s[j][1] = exp2p(fmaf(s[j][1], KSCL, -m0));
            s[j][2] = exp2p(fmaf(s[j][2], KSCL, -m1));
            s[j][3] = exp2p(fmaf(s[j][3], KSCL, -m1));
            rs0 += s[j][0] + s[j][1];
            rs1 += s[j][2] + s[j][3];
        }
#pragma unroll
        for (int ofs = 1; ofs <= 2; ofs <<= 1) {
            rs0 += __shfl_xor_sync(0xffffffffu, rs0, ofs);
            rs1 += __shfl_xor_sync(0xffffffffu, rs1, ofs);
        }
        l0 = l0 * a0 + rs0;
        l1 = l1 * a1 + rs1;
#pragma unroll
        for (int j = 0; j < 8; j++) {
            o[j][0] *= a0; o[j][1] *= a0;
            o[j][2] *= a1; o[j][3] *= a1;
        }

        /* ---- O += Ph*Vh + Pl*Vh + Ph*Vl, V-cols in pairs: 4-acc ---- */
#pragma unroll
        for (int ks = 0; ks < 8; ks++) {
            uint32_t pah[4], pal[4];
            split2(s[2 * ks][0],     s[2 * ks][1],     pah[0], pal[0]);
            split2(s[2 * ks][2],     s[2 * ks][3],     pah[1], pal[1]);
            split2(s[2 * ks + 1][0], s[2 * ks + 1][1], pah[2], pal[2]);
            split2(s[2 * ks + 1][2], s[2 * ks + 1][3], pah[3], pal[3]);
            int vr = ks * 16 + lr;
#pragma unroll
            for (int jpp = 0; jpp < 2; jpp++) {
                int offV0 = vr * 128 + (((4 * jpp + lg)     ^ (vr & 7)) << 4);
                int offV1 = vr * 128 + (((4 * jpp + 2 + lg) ^ (vr & 7)) << 4);
                uint32_t vhA[4], vlA[4], vhB[4], vlB[4];
                ldsm4t(vhA, sVh + offV0);
                ldsm4t(vlA, sVl + offV0);
                ldsm4t(vhB, sVh + offV1);
                ldsm4t(vlB, sVl + offV1);
                float* o0 = o[4 * jpp];     float* o1 = o[4 * jpp + 1];
                float* o2 = o[4 * jpp + 2]; float* o3 = o[4 * jpp + 3];
                mmabf(o0, pah, vhA[0], vhA[1]);
                mmabf(o1, pah, vhA[2], vhA[3]);
                mmabf(o2, pah, vhB[0], vhB[1]);
                mmabf(o3, pah, vhB[2], vhB[3]);
                mmabf(o0, pal, vhA[0], vhA[1]);
                mmabf(o1, pal, vhA[2], vhA[3]);
                mmabf(o2, pal, vhB[0], vhB[1]);
                mmabf(o3, pal, vhB[2], vhB[3]);
                mmabf(o0, pah, vlA[0], vlA[1]);
                mmabf(o1, pah, vlA[2], vlA[3]);
                mmabf(o2, pah, vlB[0], vlB[1]);
                mmabf(o3, pah, vlB[2], vlB[3]);
            }
        }
        __syncthreads();
        if (it + 2 < SEQ / 128) kvload(it & 1, (it + 2) * 128);
    }

    /* epilogue: normalize and write bf16 hi/lo */
    float i0 = 1.f / l0, i1 = 1.f / l1;
    size_t r0 = rbase + q0 + w * 16 + g4;
#pragma unroll
    for (int jn = 0; jn < 8; jn++) {
        int col = qoff + jn * 8 + l4 * 2;
        uint32_t hh, ll;
        split2(o[jn][0] * i0, o[jn][1] * i0, hh, ll);
        *(uint32_t*)(oh + r0 * DM + col) = hh;
        *(uint32_t*)(ol + r0 * DM + col) = ll;
        split2(o[jn][2] * i1, o[jn][3] * i1, hh, ll);
        *(uint32_t*)(oh + (r0 + 8) * DM + col) = hh;
        *(uint32_t*)(ol + (r0 + 8) * DM + col) = ll;
    }
}

/* ------------------------------------------------------------------ */
extern "C" void kernel_launch(void* const* d_in, const int* in_sizes, int n_in,
                              void* d_out, int out_size)
{
    (void)in_sizes; (void)n_in; (void)out_size;
    const float* x     = (const float*)d_in[0];
    const float* w_qkv = (const float*)d_in[1];
    const float* b_qkv = (const float*)d_in[2];
    const float* w_out = (const float*)d_in[3];
    const float* b_out = (const float*)d_in[4];
    float* out = (float*)d_out;

    bf16 *xh, *xl, *wqh, *wql, *woh, *wol, *qkvh, *qkvl, *ah, *al;
    cudaGetSymbolAddress((void**)&xh,   g_xh);
    cudaGetSymbolAddress((void**)&xl,   g_xl);
    cudaGetSymbolAddress((void**)&wqh,  g_wqh);
    cudaGetSymbolAddress((void**)&wql,  g_wql);
    cudaGetSymbolAddress((void**)&woh,  g_woh);
    cudaGetSymbolAddress((void**)&wol,  g_wol);
    cudaGetSymbolAddress((void**)&qkvh, g_qkvh);
    cudaGetSymbolAddress((void**)&qkvl, g_qkvl);
    cudaGetSymbolAddress((void**)&ah,   g_ah);
    cudaGetSymbolAddress((void**)&al,   g_al);

    cudaFuncSetAttribute(flash_mma_kernel,
                         cudaFuncAttributeMaxDynamicSharedMemorySize, FLASH_SMEM);
    cudaFuncSetAttribute(gemm_mma_kernel<1>,
                         cudaFuncAttributeMaxDynamicSharedMemorySize, GEMM_SMEM);
    cudaFuncSetAttribute(gemm_mma_kernel<0>,
                         cudaFuncAttributeMaxDynamicSharedMemorySize, GEMM_SMEM);

    /* 0) precision-split inputs + transposed weights */
    split_kernel<<<(ROWS * DM / 4 + 255) / 256, 256>>>(x, xh, xl, ROWS * DM / 4);
    transpose_split_kernel<<<dim3(QC / 32, DM / 32), dim3(32, 8)>>>(w_qkv, wqh, wql, QC);
    transpose_split_kernel<<<dim3(DM / 32, DM / 32), dim3(32, 8)>>>(w_out, woh, wol, DM);

    /* 1) QKV projection (writes bf16 hi/lo directly) */
    gemm_mma_kernel<1><<<dim3(QC / 128, ROWS / 256), 256, GEMM_SMEM>>>(
        xh, xl, wqh, wql, b_qkv, nullptr, qkvh, qkvl, QC);

    /* 2) flash attention (writes bf16 hi/lo) */
    flash_mma_kernel<<<dim3(SEQ / 128, BATCH * NH), 256, FLASH_SMEM>>>(
        qkvh, qkvl, ah, al);

    /* 3) output projection (writes fp32 final) */
    gemm_mma_kernel<0><<<dim3(DM / 128, ROWS / 256), 256, GEMM_SMEM>>>(
        ah, al, woh, wol, b_out, out, nullptr, nullptr, DM);
}

// round 10
// speedup vs baseline: 2.9170x; 1.0564x over previous
#include <cuda_runtime.h>
#include <cuda_bf16.h>
#include <stdint.h>

typedef __nv_bfloat16  bf16;
typedef __nv_bfloat162 bf162;

#define BATCH 4
#define SEQ   2048
#define DM    1024
#define NH    16
#define HD    64
#define ROWS  8192
#define QC    3072
/* 0.125 * log2(e) : softmax computed in base-2 domain */
#define KSCL  0.1803368801111204f

/* ---------------- scratch (__device__ globals) --------------------- */
__device__ bf16 g_xh[(size_t)ROWS * DM];
__device__ bf16 g_xl[(size_t)ROWS * DM];
__device__ bf16 g_wqh[(size_t)QC * DM];
__device__ bf16 g_wql[(size_t)QC * DM];
__device__ bf16 g_woh[(size_t)DM * DM];
__device__ bf16 g_wol[(size_t)DM * DM];
__device__ bf16 g_qkvh[(size_t)ROWS * QC];
__device__ bf16 g_qkvl[(size_t)ROWS * QC];
__device__ bf16 g_ah[(size_t)ROWS * DM];
__device__ bf16 g_al[(size_t)ROWS * DM];

/* ---------------- helpers ------------------------------------------ */
__device__ __forceinline__ uint32_t s2u(const void* p) {
    uint32_t a;
    asm("{ .reg .u64 t; cvta.to.shared.u64 t, %1; cvt.u32.u64 %0, t; }"
        : "=r"(a) : "l"(p));
    return a;
}
__device__ __forceinline__ void ldsm4(uint32_t* d, uint32_t a) {
    asm volatile("ldmatrix.sync.aligned.m8n8.x4.shared.b16 {%0,%1,%2,%3}, [%4];"
        : "=r"(d[0]), "=r"(d[1]), "=r"(d[2]), "=r"(d[3]) : "r"(a));
}
__device__ __forceinline__ void ldsm4t(uint32_t* d, uint32_t a) {
    asm volatile("ldmatrix.sync.aligned.m8n8.x4.trans.shared.b16 {%0,%1,%2,%3}, [%4];"
        : "=r"(d[0]), "=r"(d[1]), "=r"(d[2]), "=r"(d[3]) : "r"(a));
}
__device__ __forceinline__ void mmabf(float* c, const uint32_t* a,
                                      uint32_t b0, uint32_t b1) {
    asm volatile("mma.sync.aligned.m16n8k16.row.col.f32.bf16.bf16.f32 "
        "{%0,%1,%2,%3}, {%4,%5,%6,%7}, {%8,%9}, {%0,%1,%2,%3};"
        : "+f"(c[0]), "+f"(c[1]), "+f"(c[2]), "+f"(c[3])
        : "r"(a[0]), "r"(a[1]), "r"(a[2]), "r"(a[3]), "r"(b0), "r"(b1));
}
#define CP16(s, g) \
    asm volatile("cp.async.cg.shared.global [%0], [%1], 16;" :: "r"(s), "l"(g))
#define CPCOMMIT() asm volatile("cp.async.commit_group;" ::: "memory")
#define CPWAIT(n)  asm volatile("cp.async.wait_group %0;" :: "n"(n) : "memory")

/* exp2 on the FMA pipe (deg-5 poly around 0, |f|<=0.5, rel err ~2e-6) */
__device__ __forceinline__ float exp2p(float x) {
    x = fmaxf(x, -100.f);
    int i = __float2int_rn(x);
    float f = x - (float)i;
    float p = fmaf(1.3333558146e-3f, f, 9.6181291076e-3f);
    p = fmaf(p, f, 5.5504108664e-2f);
    p = fmaf(p, f, 2.4022650696e-1f);
    p = fmaf(p, f, 6.9314718056e-1f);
    p = fmaf(p, f, 1.0f);
    return p * __int_as_float((i + 127) << 23);
}
/* split (v0,v1) fp32 -> bf16x2 hi (round-nearest) + bf16x2 residual */
__device__ __forceinline__ void split2(float v0, float v1,
                                       uint32_t& hi, uint32_t& lo) {
    bf16 h0 = __float2bfloat16(v0), h1 = __float2bfloat16(v1);
    bf162 H; H.x = h0; H.y = h1;
    bf162 L;
    L.x = __float2bfloat16(v0 - __bfloat162float(h0));
    L.y = __float2bfloat16(v1 - __bfloat162float(h1));
    hi = *(uint32_t*)&H; lo = *(uint32_t*)&L;
}

/* ---------------- fp32 -> bf16 hi/lo split kernels ------------------ */
__global__ __launch_bounds__(256) void split_kernel(
    const float* __restrict__ in, bf16* __restrict__ hi,
    bf16* __restrict__ lo, int n4)
{
    int i = blockIdx.x * 256 + threadIdx.x;
    if (i >= n4) return;
    float4 v = ((const float4*)in)[i];
    uint32_t h0, l0, h1, l1;
    split2(v.x, v.y, h0, l0);
    split2(v.z, v.w, h1, l1);
    ((uint32_t*)hi)[2 * i] = h0; ((uint32_t*)hi)[2 * i + 1] = h1;
    ((uint32_t*)lo)[2 * i] = l0; ((uint32_t*)lo)[2 * i + 1] = l1;
}

/* w [1024, Ncols] fp32 -> wT hi/lo [Ncols, 1024] bf16 (K contiguous) */
__global__ __launch_bounds__(256) void transpose_split_kernel(
    const float* __restrict__ w, bf16* __restrict__ th,
    bf16* __restrict__ tl, int Ncols)
{
    __shared__ float t[32][33];
    int n0 = blockIdx.x * 32, k0 = blockIdx.y * 32;
    int tx = threadIdx.x, ty = threadIdx.y;   /* block (32,8) */
#pragma unroll
    for (int i = 0; i < 4; i++)
        t[ty + 8 * i][tx] = w[(size_t)(k0 + ty + 8 * i) * Ncols + n0 + tx];
    __syncthreads();
#pragma unroll
    for (int i = 0; i < 4; i++) {
        float v = t[tx][ty + 8 * i];
        bf16 h = __float2bfloat16(v);
        size_t o = (size_t)(n0 + ty + 8 * i) * DM + k0 + tx;
        th[o] = h;
        tl[o] = __float2bfloat16(v - __bfloat162float(h));
    }
}

/* ------------------------------------------------------------------ */
/* GEMM v3: C[M,N] = A[M,K] * B[N,K]^T + bias, 3-term bf16 split.      */
/* Block 128x128, warp tile 64x32 (8 warps 2x4), BK=32, 3-stage        */
/* cp.async pipeline, __launch_bounds__(256,2) -> 2 CTAs/SM.           */
/* ------------------------------------------------------------------ */
#define GSTG  32768                     /* bytes per stage */
#define GEMM_SMEM (3 * GSTG)            /* 96 KB */

template<int SPLIT_OUT>
__global__ __launch_bounds__(256, 2) void gemm_mma_kernel(
    const bf16* __restrict__ Ah, const bf16* __restrict__ Al,
    const bf16* __restrict__ Bh, const bf16* __restrict__ Bl,
    const float* __restrict__ bias, float* __restrict__ Cf,
    bf16* __restrict__ Ch, bf16* __restrict__ Cl, int N)
{
    extern __shared__ __align__(1024) char sm[];
    const uint32_t sb = s2u(sm);
    const int tid = threadIdx.x, w = tid >> 5, lane = tid & 31;
    const int wm = w >> 2, wn = w & 3;      /* 2 x 4 warp grid */
    const int m0 = blockIdx.y << 7, n0 = blockIdx.x << 7;

    const int lr  = lane & 15;                       /* A-type ld row  */
    const int lg  = lane >> 4;                       /* A-type granule */
    const int brr = (lane & 7) + ((lane & 16) >> 1); /* B-type ld row  */
    const int bg  = (lane >> 3) & 1;                 /* B-type granule */
    const int g4  = lane >> 2, l4 = lane & 3;

    float c[4][4][4];                        /* 64 accumulator regs */
#pragma unroll
    for (int i = 0; i < 4; i++)
#pragma unroll
        for (int j = 0; j < 4; j++)
#pragma unroll
            for (int e = 0; e < 4; e++) c[i][j][e] = 0.f;

    /* cp.async one stage: Ah/Al/Bh/Bl 128x32 each, swizzled 64B rows */
    auto issue = [&](int stg, int k0) {
        uint32_t base = sb + stg * GSTG;
#pragma unroll
        for (int j = 0; j < 2; j++) {
            int idx = tid + j * 256, r = idx >> 2, g = idx & 3;
            uint32_t off = r * 64 + ((g ^ (r & 3)) << 4);
            size_t ga = (size_t)(m0 + r) * DM + k0 + g * 8;
            size_t gb = (size_t)(n0 + r) * DM + k0 + g * 8;
            CP16(base + off,          Ah + ga);
            CP16(base + 8192  + off,  Al + ga);
            CP16(base + 16384 + off,  Bh + gb);
            CP16(base + 24576 + off,  Bl + gb);
        }
        CPCOMMIT();
    };

    issue(0, 0); issue(1, 32); issue(2, 64);

#pragma unroll 1
    for (int s = 0; s < 32; s++) {
        CPWAIT(2);
        __syncthreads();
        uint32_t base = sb + (s % 3) * GSTG;
#pragma unroll
        for (int ks = 0; ks < 2; ks++) {
            /* B fragments for this warp's 32 columns (both 16-col tiles) */
            uint32_t bh[2][4], bl[2][4];
#pragma unroll
            for (int jp = 0; jp < 2; jp++) {
                int rb = wn * 32 + jp * 16 + brr;
                uint32_t offB = rb * 64 + (((2 * ks + bg) ^ (rb & 3)) << 4);
                ldsm4(bh[jp], base + 16384 + offB);
                ldsm4(bl[jp], base + 24576 + offB);
            }
#pragma unroll
            for (int im = 0; im < 4; im++) {
                int ar = wm * 64 + im * 16 + lr;
                uint32_t offA = ar * 64 + (((2 * ks + lg) ^ (ar & 3)) << 4);
                uint32_t ah[4], al[4];
                ldsm4(ah, base + offA);
                ldsm4(al, base + 8192 + offA);
#pragma unroll
                for (int jp = 0; jp < 2; jp++) {
                    mmabf(c[im][2 * jp],     ah, bh[jp][0], bh[jp][1]);
                    mmabf(c[im][2 * jp + 1], ah, bh[jp][2], bh[jp][3]);
                    mmabf(c[im][2 * jp],     ah, bl[jp][0], bl[jp][1]);
                    mmabf(c[im][2 * jp + 1], ah, bl[jp][2], bl[jp][3]);
                    mmabf(c[im][2 * jp],     al, bh[jp][0], bh[jp][1]);
                    mmabf(c[im][2 * jp + 1], al, bh[jp][2], bh[jp][3]);
                }
            }
        }
        __syncthreads();
        if (s + 3 < 32) issue(s % 3, (s + 3) * 32);
    }

    /* epilogue */
#pragma unroll
    for (int im = 0; im < 4; im++) {
#pragma unroll
        for (int jn = 0; jn < 4; jn++) {
            int row = m0 + wm * 64 + im * 16 + g4;
            int col = n0 + wn * 32 + jn * 8 + l4 * 2;
            float2 bb = *(const float2*)(bias + col);
            float v0 = c[im][jn][0] + bb.x, v1 = c[im][jn][1] + bb.y;
            float v2 = c[im][jn][2] + bb.x, v3 = c[im][jn][3] + bb.y;
            if (SPLIT_OUT) {
                uint32_t h, l;
                split2(v0, v1, h, l);
                *(uint32_t*)(Ch + (size_t)row * N + col) = h;
                *(uint32_t*)(Cl + (size_t)row * N + col) = l;
                split2(v2, v3, h, l);
                *(uint32_t*)(Ch + (size_t)(row + 8) * N + col) = h;
                *(uint32_t*)(Cl + (size_t)(row + 8) * N + col) = l;
            } else {
                *(float2*)(Cf + (size_t)row * N + col)       = make_float2(v0, v1);
                *(float2*)(Cf + (size_t)(row + 8) * N + col) = make_float2(v2, v3);
            }
        }
    }
}

/* ------------------------------------------------------------------ */
/* Flash attention, FA2-style on mma.sync. BM=BN=128, 8 warps x 16 rows*/
/* S: 3-term split; P: 2-term split; KV double-buffered via cp.async.  */
/* (unchanged from round 9 — flash occupancy is next round's variable) */
/* ------------------------------------------------------------------ */
#define KVSTG 65536
#define FLASH_SMEM (32768 + 2 * KVSTG)   /* 160 KB */

__global__ __launch_bounds__(256, 1) void flash_mma_kernel(
    const bf16* __restrict__ qh, const bf16* __restrict__ ql,
    bf16* __restrict__ oh, bf16* __restrict__ ol)
{
    extern __shared__ __align__(1024) char sm[];
    const uint32_t sQh = s2u(sm);
    const uint32_t sQl = sQh + 16384;
    const int tid = threadIdx.x, w = tid >> 5, lane = tid & 31;
    const int q0 = blockIdx.x << 7;
    const int b  = blockIdx.y >> 4, h = blockIdx.y & 15;
    const size_t rbase = (size_t)b * SEQ;
    const int qoff = h * HD, koff = DM + h * HD, voff = 2 * DM + h * HD;

    const int lr  = lane & 15;
    const int lg  = lane >> 4;
    const int brr = (lane & 7) + ((lane & 16) >> 1);
    const int bg  = (lane >> 3) & 1;
    const int g4  = lane >> 2, l4 = lane & 3;
    const int qrow = w * 16 + lr;

    /* cp.async one KV stage (Kh,Kl,Vh,Vl: 128x64 each, 128B rows) */
    auto kvload = [&](int stg, int kt) {
        uint32_t base = sQh + 32768 + stg * KVSTG;
#pragma unroll
        for (int j = 0; j < 4; j++) {
            int idx = tid + j * 256, rr = idx >> 3, g = idx & 7;
            size_t go = (rbase + kt + rr) * QC + g * 8;
            uint32_t off = rr * 128 + ((g ^ (rr & 7)) << 4);
            CP16(base + off,          qh + go + koff);
            CP16(base + 16384 + off,  ql + go + koff);
            CP16(base + 32768 + off,  qh + go + voff);
            CP16(base + 49152 + off,  ql + go + voff);
        }
        CPCOMMIT();
    };

    /* load Q tiles (hi & lo) */
#pragma unroll
    for (int it = 0; it < 4; it++) {
        int idx = tid + it * 256, rr = idx >> 3, g = idx & 7;
        size_t go = (rbase + q0 + rr) * QC + qoff + g * 8;
        int so = rr * 128 + ((g ^ (rr & 7)) << 4);
        *(uint4*)(sm + so)         = *(const uint4*)(qh + go);
        *(uint4*)(sm + 16384 + so) = *(const uint4*)(ql + go);
    }
    kvload(0, 0);
    kvload(1, 128);

    float o[8][4];
#pragma unroll
    for (int j = 0; j < 8; j++)
#pragma unroll
        for (int e = 0; e < 4; e++) o[j][e] = 0.f;
    float m0 = -1e30f, m1 = -1e30f, l0 = 0.f, l1 = 0.f;

#pragma unroll 1
    for (int it = 0; it < SEQ / 128; it++) {
        CPWAIT(1);
        __syncthreads();
        const uint32_t sKh = sQh + 32768 + (it & 1) * KVSTG;
        const uint32_t sKl = sKh + 16384, sVh = sKh + 32768, sVl = sKh + 49152;

        /* ---- S = Q K^T (3 products), K-rows in pairs: 4-acc rotation */
        float s[16][4];
#pragma unroll
        for (int j = 0; j < 16; j++)
#pragma unroll
            for (int e = 0; e < 4; e++) s[j][e] = 0.f;

#pragma unroll
        for (int ks = 0; ks < 4; ks++) {
            uint32_t ah[4], al[4];
            int offA = qrow * 128 + (((2 * ks + lg) ^ (qrow & 7)) << 4);
            ldsm4(ah, sQh + offA);
            ldsm4(al, sQl + offA);
#pragma unroll
            for (int jpp = 0; jpp < 4; jpp++) {
                int rb0 = (2 * jpp) * 16 + brr;
                int rb1 = (2 * jpp + 1) * 16 + brr;
                int offB0 = rb0 * 128 + (((2 * ks + bg) ^ (rb0 & 7)) << 4);
                int offB1 = rb1 * 128 + (((2 * ks + bg) ^ (rb1 & 7)) << 4);
                uint32_t bhA[4], blA[4], bhB[4], blB[4];
                ldsm4(bhA, sKh + offB0);
                ldsm4(blA, sKl + offB0);
                ldsm4(bhB, sKh + offB1);
                ldsm4(blB, sKl + offB1);
                float* s0 = s[4 * jpp];     float* s1 = s[4 * jpp + 1];
                float* s2 = s[4 * jpp + 2]; float* s3 = s[4 * jpp + 3];
                mmabf(s0, ah, bhA[0], bhA[1]);
                mmabf(s1, ah, bhA[2], bhA[3]);
                mmabf(s2, ah, bhB[0], bhB[1]);
                mmabf(s3, ah, bhB[2], bhB[3]);
                mmabf(s0, ah, blA[0], blA[1]);
                mmabf(s1, ah, blA[2], blA[3]);
                mmabf(s2, ah, blB[0], blB[1]);
                mmabf(s3, ah, blB[2], blB[3]);
                mmabf(s0, al, bhA[0], bhA[1]);
                mmabf(s1, al, bhA[2], bhA[3]);
                mmabf(s2, al, bhB[0], bhB[1]);
                mmabf(s3, al, bhB[2], bhB[3]);
            }
        }

        /* ---- online softmax (base-2 domain, FMA-pipe exp2) ---- */
        float mx0 = -1e30f, mx1 = -1e30f;
#pragma unroll
        for (int j = 0; j < 16; j++) {
            mx0 = fmaxf(mx0, fmaxf(s[j][0], s[j][1]));
            mx1 = fmaxf(mx1, fmaxf(s[j][2], s[j][3]));
        }
        mx0 *= KSCL; mx1 *= KSCL;
#pragma unroll
        for (int ofs = 1; ofs <= 2; ofs <<= 1) {
            mx0 = fmaxf(mx0, __shfl_xor_sync(0xffffffffu, mx0, ofs));
            mx1 = fmaxf(mx1, __shfl_xor_sync(0xffffffffu, mx1, ofs));
        }
        float nm0 = fmaxf(m0, mx0), nm1 = fmaxf(m1, mx1);
        float a0 = exp2p(m0 - nm0), a1 = exp2p(m1 - nm1);
        m0 = nm0; m1 = nm1;

        float rs0 = 0.f, rs1 = 0.f;
#pragma unroll
        for (int j = 0; j < 16; j++) {
            s[j][0] = exp2p(fmaf(s[j][0], KSCL, -m0));
            s[j][1] = exp2p(fmaf(s[j][1], KSCL, -m0));
            s[j][2] = exp2p(fmaf(s[j][2], KSCL, -m1));
            s[j][3] = exp2p(fmaf(s[j][3], KSCL, -m1));
            rs0 += s[j][0] + s[j][1];
            rs1 += s[j][2] + s[j][3];
        }
#pragma unroll
        for (int ofs = 1; ofs <= 2; ofs <<= 1) {
            rs0 += __shfl_xor_sync(0xffffffffu, rs0, ofs);
            rs1 += __shfl_xor_sync(0xffffffffu, rs1, ofs);
        }
        l0 = l0 * a0 + rs0;
        l1 = l1 * a1 + rs1;
#pragma unroll
        for (int j = 0; j < 8; j++) {
            o[j][0] *= a0; o[j][1] *= a0;
            o[j][2] *= a1; o[j][3] *= a1;
        }

        /* ---- O += Ph*Vh + Pl*Vh + Ph*Vl, V-cols in pairs: 4-acc ---- */
#pragma unroll
        for (int ks = 0; ks < 8; ks++) {
            uint32_t pah[4], pal[4];
            split2(s[2 * ks][0],     s[2 * ks][1],     pah[0], pal[0]);
            split2(s[2 * ks][2],     s[2 * ks][3],     pah[1], pal[1]);
            split2(s[2 * ks + 1][0], s[2 * ks + 1][1], pah[2], pal[2]);
            split2(s[2 * ks + 1][2], s[2 * ks + 1][3], pah[3], pal[3]);
            int vr = ks * 16 + lr;
#pragma unroll
            for (int jpp = 0; jpp < 2; jpp++) {
                int offV0 = vr * 128 + (((4 * jpp + lg)     ^ (vr & 7)) << 4);
                int offV1 = vr * 128 + (((4 * jpp + 2 + lg) ^ (vr & 7)) << 4);
                uint32_t vhA[4], vlA[4], vhB[4], vlB[4];
                ldsm4t(vhA, sVh + offV0);
                ldsm4t(vlA, sVl + offV0);
                ldsm4t(vhB, sVh + offV1);
                ldsm4t(vlB, sVl + offV1);
                float* o0 = o[4 * jpp];     float* o1 = o[4 * jpp + 1];
                float* o2 = o[4 * jpp + 2]; float* o3 = o[4 * jpp + 3];
                mmabf(o0, pah, vhA[0], vhA[1]);
                mmabf(o1, pah, vhA[2], vhA[3]);
                mmabf(o2, pah, vhB[0], vhB[1]);
                mmabf(o3, pah, vhB[2], vhB[3]);
                mmabf(o0, pal, vhA[0], vhA[1]);
                mmabf(o1, pal, vhA[2], vhA[3]);
                mmabf(o2, pal, vhB[0], vhB[1]);
                mmabf(o3, pal, vhB[2], vhB[3]);
                mmabf(o0, pah, vlA[0], vlA[1]);
                mmabf(o1, pah, vlA[2], vlA[3]);
                mmabf(o2, pah, vlB[0], vlB[1]);
                mmabf(o3, pah, vlB[2], vlB[3]);
            }
        }
        __syncthreads();
        if (it + 2 < SEQ / 128) kvload(it & 1, (it + 2) * 128);
    }

    /* epilogue: normalize and write bf16 hi/lo */
    float i0 = 1.f / l0, i1 = 1.f / l1;
    size_t r0 = rbase + q0 + w * 16 + g4;
#pragma unroll
    for (int jn = 0; jn < 8; jn++) {
        int col = qoff + jn * 8 + l4 * 2;
        uint32_t hh, ll;
        split2(o[jn][0] * i0, o[jn][1] * i0, hh, ll);
        *(uint32_t*)(oh + r0 * DM + col) = hh;
        *(uint32_t*)(ol + r0 * DM + col) = ll;
        split2(o[jn][2] * i1, o[jn][3] * i1, hh, ll);
        *(uint32_t*)(oh + (r0 + 8) * DM + col) = hh;
        *(uint32_t*)(ol + (r0 + 8) * DM + col) = ll;
    }
}

/* ------------------------------------------------------------------ */
extern "C" void kernel_launch(void* const* d_in, const int* in_sizes, int n_in,
                              void* d_out, int out_size)
{
    (void)in_sizes; (void)n_in; (void)out_size;
    const float* x     = (const float*)d_in[0];
    const float* w_qkv = (const float*)d_in[1];
    const float* b_qkv = (const float*)d_in[2];
    const float* w_out = (const float*)d_in[3];
    const float* b_out = (const float*)d_in[4];
    float* out = (float*)d_out;

    bf16 *xh, *xl, *wqh, *wql, *woh, *wol, *qkvh, *qkvl, *ah, *al;
    cudaGetSymbolAddress((void**)&xh,   g_xh);
    cudaGetSymbolAddress((void**)&xl,   g_xl);
    cudaGetSymbolAddress((void**)&wqh,  g_wqh);
    cudaGetSymbolAddress((void**)&wql,  g_wql);
    cudaGetSymbolAddress((void**)&woh,  g_woh);
    cudaGetSymbolAddress((void**)&wol,  g_wol);
    cudaGetSymbolAddress((void**)&qkvh, g_qkvh);
    cudaGetSymbolAddress((void**)&qkvl, g_qkvl);
    cudaGetSymbolAddress((void**)&ah,   g_ah);
    cudaGetSymbolAddress((void**)&al,   g_al);

    cudaFuncSetAttribute(flash_mma_kernel,
                         cudaFuncAttributeMaxDynamicSharedMemorySize, FLASH_SMEM);
    cudaFuncSetAttribute(gemm_mma_kernel<1>,
                         cudaFuncAttributeMaxDynamicSharedMemorySize, GEMM_SMEM);
    cudaFuncSetAttribute(gemm_mma_kernel<0>,
                         cudaFuncAttributeMaxDynamicSharedMemorySize, GEMM_SMEM);

    /* 0) precision-split inputs + transposed weights */
    split_kernel<<<(ROWS * DM / 4 + 255) / 256, 256>>>(x, xh, xl, ROWS * DM / 4);
    transpose_split_kernel<<<dim3(QC / 32, DM / 32), dim3(32, 8)>>>(w_qkv, wqh, wql, QC);
    transpose_split_kernel<<<dim3(DM / 32, DM / 32), dim3(32, 8)>>>(w_out, woh, wol, DM);

    /* 1) QKV projection (writes bf16 hi/lo directly) */
    gemm_mma_kernel<1><<<dim3(QC / 128, ROWS / 128), 256, GEMM_SMEM>>>(
        xh, xl, wqh, wql, b_qkv, nullptr, qkvh, qkvl, QC);

    /* 2) flash attention (writes bf16 hi/lo) */
    flash_mma_kernel<<<dim3(SEQ / 128, BATCH * NH), 256, FLASH_SMEM>>>(
        qkvh, qkvl, ah, al);

    /* 3) output projection (writes fp32 final) */
    gemm_mma_kernel<0><<<dim3(DM / 128, ROWS / 128), 256, GEMM_SMEM>>>(
        ah, al, woh, wol, b_out, out, nullptr, nullptr, DM);
}